// round 1
// baseline (speedup 1.0000x reference)
#include <cuda_runtime.h>
#include <math.h>

#define D_  1024
#define H_  16
#define DH_ 64
#define F_  4096
#define E_  8
#define K_  2
#define B_  2
#define S_  2048
#define N_  (B_ * S_)          // 4096 tokens
#define BH_ (B_ * H_)          // 32
#define ND_ ((long)N_ * D_)    // 4194304

// ---------------- scratch (device globals; no allocation allowed) -------------
__device__ float g_q[N_ * D_];
__device__ float g_k[N_ * D_];
__device__ float g_v[N_ * D_];
__device__ float g_attn[N_ * D_];
__device__ float g_t[N_ * D_];
__device__ float g_x1[N_ * D_];
__device__ float g_x2[N_ * D_];
__device__ float g_moe[N_ * D_];
// big scratch: attention probabilities (32 * 2048 * 2048 floats = 512MB),
// later reused as the MoE hidden activations (8192 * 4096 floats = 128MB).
__device__ float g_s[(long)BH_ * S_ * S_];

__device__ int   g_topi[N_ * K_];
__device__ float g_gate[N_ * K_];
__device__ int   g_cnt[E_];
__device__ int   g_off[E_];
__device__ int   g_cur[E_];
__device__ int   g_dtok[N_ * K_];
__device__ float g_dgate[N_ * K_];
__device__ float g_probs[N_ * E_];
__device__ int   g_loadcnt[E_];

// ---------------- generic tiled fp32 GEMM core -------------------------------
// Block tile: 128 x BNv, K-step 16, 256 threads, each thread 8 x TNv.
#define TBM 128
#define TBK 16

template<int BNv, int TNv, bool TRANSB, bool GATHER, bool RELU, bool SCATTER>
__device__ __forceinline__ void gemm_block(
    const float* __restrict__ A, int lda,
    const float* __restrict__ B, int ldb,
    float* __restrict__ C, int ldc,
    int M, int N, int K,
    const float* __restrict__ bias,
    const int* __restrict__ gidx,      // gather rows for A (GATHER)
    const int* __restrict__ sidx,      // scatter rows for C (SCATTER)
    const float* __restrict__ rscale)  // per-row scale (SCATTER)
{
    __shared__ float As[TBK][TBM + 4];
    __shared__ float Bs[TBK][BNv + 4];

    const int tid = threadIdx.x;
    const int m0 = blockIdx.y * TBM;
    const int n0 = blockIdx.x * BNv;
    if (m0 >= M) return;

    const int tx = tid & 15;
    const int ty = tid >> 4;

    float acc[8][TNv];
#pragma unroll
    for (int i = 0; i < 8; i++)
#pragma unroll
        for (int j = 0; j < TNv; j++) acc[i][j] = 0.f;

    // A loader: 128 rows x 16 cols, 8 floats/thread
    const int ar = tid >> 1;
    const int ac = (tid & 1) * 8;
    const bool avalid = (m0 + ar) < M;
    const float* Ap = A;  // dummy init
    if (avalid) {
        long grow = GATHER ? (long)gidx[m0 + ar] : (long)(m0 + ar);
        Ap = A + grow * (long)lda + ac;
    }

    constexpr int CPT = BNv / 16;  // B floats per thread (8 or 4)

    for (int k0 = 0; k0 < K; k0 += TBK) {
        // ---- load A tile (transposed into smem) ----
        if (avalid) {
            float4 a0 = *(const float4*)(Ap + k0);
            float4 a1 = *(const float4*)(Ap + k0 + 4);
            As[ac + 0][ar] = a0.x; As[ac + 1][ar] = a0.y;
            As[ac + 2][ar] = a0.z; As[ac + 3][ar] = a0.w;
            As[ac + 4][ar] = a1.x; As[ac + 5][ar] = a1.y;
            As[ac + 6][ar] = a1.z; As[ac + 7][ar] = a1.w;
        } else {
#pragma unroll
            for (int i = 0; i < 8; i++) As[ac + i][ar] = 0.f;
        }
        // ---- load B tile ----
        if constexpr (TRANSB) {
            // logical B[k][n] stored as Bphys[n][k]; tile = BNv n-rows x 16 k-cols
            constexpr int TPR = 16 / CPT;           // threads per n-row
            const int brow = tid / TPR;
            const int bc = (tid % TPR) * CPT;
            if (n0 + brow < N) {
                const float* bp = B + (long)(n0 + brow) * ldb + k0 + bc;
#pragma unroll
                for (int v = 0; v < CPT; v += 4) {
                    float4 b4 = *(const float4*)(bp + v);
                    Bs[bc + v + 0][brow] = b4.x;
                    Bs[bc + v + 1][brow] = b4.y;
                    Bs[bc + v + 2][brow] = b4.z;
                    Bs[bc + v + 3][brow] = b4.w;
                }
            } else {
#pragma unroll
                for (int v = 0; v < CPT; v++) Bs[bc + v][brow] = 0.f;
            }
        } else {
            const int br = tid >> 4;
            const int bc = (tid & 15) * CPT;
            const float* bp = B + (long)(k0 + br) * ldb + n0 + bc;
            if (n0 + bc + CPT - 1 < N) {
#pragma unroll
                for (int v = 0; v < CPT; v += 4)
                    *(float4*)&Bs[br][bc + v] = *(const float4*)(bp + v);
            } else {
#pragma unroll
                for (int v = 0; v < CPT; v++)
                    Bs[br][bc + v] = (n0 + bc + v < N) ? bp[v] : 0.f;
            }
        }
        __syncthreads();
        // ---- compute ----
#pragma unroll
        for (int kk = 0; kk < TBK; kk++) {
            float a[8], b[TNv];
            *(float4*)&a[0] = *(const float4*)&As[kk][ty * 8];
            *(float4*)&a[4] = *(const float4*)&As[kk][ty * 8 + 4];
#pragma unroll
            for (int v = 0; v < TNv; v += 4)
                *(float4*)&b[v] = *(const float4*)&Bs[kk][tx * TNv + v];
#pragma unroll
            for (int i = 0; i < 8; i++)
#pragma unroll
                for (int j = 0; j < TNv; j++)
                    acc[i][j] = fmaf(a[i], b[j], acc[i][j]);
        }
        __syncthreads();
    }

    // ---- epilogue ----
#pragma unroll
    for (int i = 0; i < 8; i++) {
        int row = m0 + ty * 8 + i;
        if (row >= M) continue;
        float sc = 1.f;
        long crow = row;
        if constexpr (SCATTER) { sc = rscale[row]; crow = sidx[row]; }
        float* cp = C + crow * (long)ldc;
#pragma unroll
        for (int j = 0; j < TNv; j++) {
            int col = n0 + tx * TNv + j;
            if (col < N) {
                float v = acc[i][j];
                if (bias) v += bias[col];
                if constexpr (RELU) v = fmaxf(v, 0.f);
                if constexpr (SCATTER) atomicAdd(cp + col, v * sc);
                else cp[col] = v;
            }
        }
    }
}

// ---------------- GEMM kernel wrappers ----------------------------------------
__global__ void __launch_bounds__(256, 2) k_gemm_bias(
    const float* __restrict__ A, const float* __restrict__ B,
    const float* __restrict__ bias, float* __restrict__ C,
    int M, int N, int K, int lda, int ldb, int ldc)
{
    gemm_block<128, 8, false, false, false, false>(A, lda, B, ldb, C, ldc,
                                                   M, N, K, bias,
                                                   nullptr, nullptr, nullptr);
}

// scores[z] = Q_z @ K_z^T   (z = b*H + h), NT layout
__global__ void __launch_bounds__(256, 2) k_scores()
{
    const int z = blockIdx.z, b = z >> 4, h = z & 15;
    const float* A = g_q + (long)b * S_ * D_ + h * DH_;
    const float* B = g_k + (long)b * S_ * D_ + h * DH_;
    float* C = g_s + (long)z * S_ * S_;
    gemm_block<128, 8, true, false, false, false>(A, D_, B, D_, C, S_,
                                                  S_, S_, DH_, nullptr,
                                                  nullptr, nullptr, nullptr);
}

// attn[z] = P_z @ V_z  (N = 64, narrow tile)
__global__ void __launch_bounds__(256, 2) k_pv()
{
    const int z = blockIdx.z, b = z >> 4, h = z & 15;
    const float* A = g_s + (long)z * S_ * S_;
    const float* B = g_v + (long)b * S_ * D_ + h * DH_;
    float* C = g_attn + (long)b * S_ * D_ + h * DH_;
    gemm_block<64, 4, false, false, false, false>(A, S_, B, D_, C, D_,
                                                  S_, DH_, S_, nullptr,
                                                  nullptr, nullptr, nullptr);
}

// MoE FF1: h = relu(gather(x2) @ W1[e] + b1[e]) into g_s (reused as hidden buf)
__global__ void __launch_bounds__(256, 2) k_ff1(
    const float* __restrict__ W1, const float* __restrict__ B1)
{
    const int e = blockIdx.z;
    const int cnt = g_cnt[e];
    if ((int)(blockIdx.y * TBM) >= cnt) return;
    const int off = g_off[e];
    gemm_block<128, 8, false, true, true, false>(
        g_x2, D_, W1 + (long)e * D_ * F_, F_,
        g_s + (long)off * F_, F_,
        cnt, F_, D_, B1 + (long)e * F_,
        g_dtok + off, nullptr, nullptr);
}

// MoE FF2: moe_out[tok] += gate * (h @ W2[e] + b2[e])   (atomic scatter)
__global__ void __launch_bounds__(256, 2) k_ff2(
    const float* __restrict__ W2, const float* __restrict__ B2)
{
    const int e = blockIdx.z;
    const int cnt = g_cnt[e];
    if ((int)(blockIdx.y * TBM) >= cnt) return;
    const int off = g_off[e];
    gemm_block<128, 8, false, false, false, true>(
        g_s + (long)off * F_, F_, W2 + (long)e * F_ * D_, D_,
        g_moe, D_, cnt, D_, F_, B2 + (long)e * D_,
        nullptr, g_dtok + off, g_dgate + off);
}

// ---------------- elementwise / softmax / LN ----------------------------------
__global__ void k_zero()
{
    long i = (long)blockIdx.x * 256 + threadIdx.x;
    if (i < ND_) g_moe[i] = 0.f;
    if (i < E_) { g_cnt[i] = 0; g_cur[i] = 0; g_loadcnt[i] = 0; }
}

// row softmax of scores with 1/sqrt(DH) scale applied inside the exp
__global__ void k_softmax()
{
    __shared__ float buf[S_];
    __shared__ float red[256];
    const long row = blockIdx.x;
    float* p = g_s + row * (long)S_;
    const int tid = threadIdx.x;
    float mx = -3.4e38f;
    for (int i = tid; i < S_; i += 256) { float v = p[i]; buf[i] = v; mx = fmaxf(mx, v); }
    red[tid] = mx; __syncthreads();
    for (int o = 128; o > 0; o >>= 1) { if (tid < o) red[tid] = fmaxf(red[tid], red[tid + o]); __syncthreads(); }
    mx = red[0]; __syncthreads();
    float sum = 0.f;
    for (int i = tid; i < S_; i += 256) { float e = expf((buf[i] - mx) * 0.125f); buf[i] = e; sum += e; }
    red[tid] = sum; __syncthreads();
    for (int o = 128; o > 0; o >>= 1) { if (tid < o) red[tid] += red[tid + o]; __syncthreads(); }
    float inv = 1.f / red[0];
    for (int i = tid; i < S_; i += 256) p[i] = buf[i] * inv;
}

// out = LayerNorm(a + b) * g + beta, one block per token
__global__ void k_addln(const float* __restrict__ a, const float* __restrict__ b,
                        const float* __restrict__ g, const float* __restrict__ be,
                        float* __restrict__ out)
{
    __shared__ float buf[D_];
    __shared__ float red[256];
    const int t = blockIdx.x;
    const int tid = threadIdx.x;
    const float* pa = a + (long)t * D_;
    const float* pb = b + (long)t * D_;
    float s = 0.f;
    for (int i = tid; i < D_; i += 256) { float v = pa[i] + pb[i]; buf[i] = v; s += v; }
    red[tid] = s; __syncthreads();
    for (int o = 128; o > 0; o >>= 1) { if (tid < o) red[tid] += red[tid + o]; __syncthreads(); }
    float mean = red[0] * (1.f / D_);
    __syncthreads();
    float vs = 0.f;
    for (int i = tid; i < D_; i += 256) { float d = buf[i] - mean; vs += d * d; }
    red[tid] = vs; __syncthreads();
    for (int o = 128; o > 0; o >>= 1) { if (tid < o) red[tid] += red[tid + o]; __syncthreads(); }
    float rstd = rsqrtf(red[0] * (1.f / D_) + 1e-5f);
    float* po = out + (long)t * D_;
    for (int i = tid; i < D_; i += 256)
        po[i] = (buf[i] - mean) * rstd * g[i] + be[i];
}

// ---------------- router / dispatch / aux --------------------------------------
// One warp per token: logits = x @ r_w + r_b, softmax over 8, top-2 w/ lowest-
// index tiebreak (matches jax.lax.top_k).
__device__ __forceinline__ void router_core(const float* __restrict__ x,
                                            const float* __restrict__ rw,
                                            const float* __restrict__ rb,
                                            int lane, float* probs_out,
                                            int* i1_out, int* i2_out)
{
    float le[E_];
#pragma unroll
    for (int e = 0; e < E_; e++) le[e] = 0.f;
    for (int d0 = lane * 4; d0 < D_; d0 += 128) {
        float4 xv = *(const float4*)(x + d0);
        float xa[4] = {xv.x, xv.y, xv.z, xv.w};
#pragma unroll
        for (int r = 0; r < 4; r++) {
            const float* w = rw + (long)(d0 + r) * E_;
            float4 w0 = *(const float4*)(w);
            float4 w1 = *(const float4*)(w + 4);
            le[0] = fmaf(xa[r], w0.x, le[0]); le[1] = fmaf(xa[r], w0.y, le[1]);
            le[2] = fmaf(xa[r], w0.z, le[2]); le[3] = fmaf(xa[r], w0.w, le[3]);
            le[4] = fmaf(xa[r], w1.x, le[4]); le[5] = fmaf(xa[r], w1.y, le[5]);
            le[6] = fmaf(xa[r], w1.z, le[6]); le[7] = fmaf(xa[r], w1.w, le[7]);
        }
    }
#pragma unroll
    for (int e = 0; e < E_; e++)
        for (int o = 16; o > 0; o >>= 1) le[e] += __shfl_xor_sync(0xffffffffu, le[e], o);
    float mx = -3.4e38f;
#pragma unroll
    for (int e = 0; e < E_; e++) { le[e] += rb[e]; mx = fmaxf(mx, le[e]); }
    float sum = 0.f;
#pragma unroll
    for (int e = 0; e < E_; e++) { le[e] = expf(le[e] - mx); sum += le[e]; }
    float inv = 1.f / sum;
#pragma unroll
    for (int e = 0; e < E_; e++) { le[e] *= inv; probs_out[e] = le[e]; }
    int i1 = 0;
    for (int e = 1; e < E_; e++) if (le[e] > le[i1]) i1 = e;
    int i2 = (i1 == 0) ? 1 : 0;
    for (int e = 0; e < E_; e++) if (e != i1 && le[e] > le[i2]) i2 = e;
    *i1_out = i1; *i2_out = i2;
}

__global__ void k_router(const float* __restrict__ rw, const float* __restrict__ rb)
{
    const int warp = threadIdx.x >> 5, lane = threadIdx.x & 31;
    const int t = blockIdx.x * 8 + warp;
    if (t >= N_) return;
    float probs[E_]; int i1, i2;
    router_core(g_x2 + (long)t * D_, rw, rb, lane, probs, &i1, &i2);
    if (lane == 0) {
        float gs = probs[i1] + probs[i2];
        g_topi[t * 2] = i1; g_topi[t * 2 + 1] = i2;
        g_gate[t * 2] = probs[i1] / gs; g_gate[t * 2 + 1] = probs[i2] / gs;
        atomicAdd(&g_cnt[i1], 1); atomicAdd(&g_cnt[i2], 1);
    }
}

__global__ void k_scan()
{
    if (threadIdx.x == 0) {
        int s = 0;
        for (int e = 0; e < E_; e++) { g_off[e] = s; s += g_cnt[e]; }
    }
}

__global__ void k_fill()
{
    int t = blockIdx.x * 256 + threadIdx.x;
    if (t >= N_) return;
#pragma unroll
    for (int k = 0; k < K_; k++) {
        int e = g_topi[t * K_ + k];
        int p = atomicAdd(&g_cur[e], 1);
        int d = g_off[e] + p;
        g_dtok[d] = t;
        g_dgate[d] = g_gate[t * K_ + k];
    }
}

// aux-loss router pass on the FINAL output
__global__ void k_aux_router(const float* __restrict__ X,
                             const float* __restrict__ rw, const float* __restrict__ rb)
{
    const int warp = threadIdx.x >> 5, lane = threadIdx.x & 31;
    const int t = blockIdx.x * 8 + warp;
    if (t >= N_) return;
    float probs[E_]; int i1, i2;
    router_core(X + (long)t * D_, rw, rb, lane, probs, &i1, &i2);
    if (lane == 0) {
#pragma unroll
        for (int e = 0; e < E_; e++) g_probs[t * E_ + e] = probs[e];
        atomicAdd(&g_loadcnt[i1], 1); atomicAdd(&g_loadcnt[i2], 1);
    }
}

// deterministic fixed-order reduction of importance; aux -> out[N*D]
__global__ void k_aux_reduce(float* __restrict__ out, int write)
{
    __shared__ float red[256];
    const int tid = threadIdx.x;
    float imp[E_];
#pragma unroll
    for (int e = 0; e < E_; e++) imp[e] = 0.f;
    for (int t = tid; t < N_; t += 256)
#pragma unroll
        for (int e = 0; e < E_; e++) imp[e] += g_probs[t * E_ + e];
    float aux = 0.f;
    for (int e = 0; e < E_; e++) {
        red[tid] = imp[e]; __syncthreads();
        for (int o = 128; o > 0; o >>= 1) { if (tid < o) red[tid] += red[tid + o]; __syncthreads(); }
        if (tid == 0)
            aux += (red[0] / (float)N_) * ((float)g_loadcnt[e] / (float)(N_ * K_));
        __syncthreads();
    }
    if (tid == 0 && write) out[ND_] = aux * (float)E_;
}

// ---------------- launch ------------------------------------------------------
extern "C" void kernel_launch(void* const* d_in, const int* in_sizes, int n_in,
                              void* d_out, int out_size)
{
    (void)in_sizes; (void)n_in;
    const float* x     = (const float*)d_in[0];
    const float* enc   = (const float*)d_in[1];
    const float* sa_wq = (const float*)d_in[2];
    const float* sa_bq = (const float*)d_in[3];
    const float* sa_wk = (const float*)d_in[4];
    const float* sa_bk = (const float*)d_in[5];
    const float* sa_wv = (const float*)d_in[6];
    const float* sa_bv = (const float*)d_in[7];
    const float* sa_wo = (const float*)d_in[8];
    const float* sa_bo = (const float*)d_in[9];
    const float* ca_wq = (const float*)d_in[10];
    const float* ca_bq = (const float*)d_in[11];
    const float* ca_wk = (const float*)d_in[12];
    const float* ca_bk = (const float*)d_in[13];
    const float* ca_wv = (const float*)d_in[14];
    const float* ca_bv = (const float*)d_in[15];
    const float* ca_wo = (const float*)d_in[16];
    const float* ca_bo = (const float*)d_in[17];
    const float* n1_g  = (const float*)d_in[18];
    const float* n1_b  = (const float*)d_in[19];
    const float* n2_g  = (const float*)d_in[20];
    const float* n2_b  = (const float*)d_in[21];
    const float* n3_g  = (const float*)d_in[22];
    const float* n3_b  = (const float*)d_in[23];
    const float* r_w   = (const float*)d_in[24];
    const float* r_b   = (const float*)d_in[25];
    const float* e_w1  = (const float*)d_in[26];
    const float* e_b1  = (const float*)d_in[27];
    const float* e_w2  = (const float*)d_in[28];
    const float* e_b2  = (const float*)d_in[29];
    float* out = (float*)d_out;

    float *pq, *pk, *pv, *pattn, *pt, *px1, *px2, *pmoe;
    cudaGetSymbolAddress((void**)&pq, g_q);
    cudaGetSymbolAddress((void**)&pk, g_k);
    cudaGetSymbolAddress((void**)&pv, g_v);
    cudaGetSymbolAddress((void**)&pattn, g_attn);
    cudaGetSymbolAddress((void**)&pt, g_t);
    cudaGetSymbolAddress((void**)&px1, g_x1);
    cudaGetSymbolAddress((void**)&px2, g_x2);
    cudaGetSymbolAddress((void**)&pmoe, g_moe);

    dim3 blk(256);
    dim3 gProj(D_ / 128, N_ / 128);            // (8, 32)
    dim3 gScores(S_ / 128, S_ / 128, BH_);     // (16, 16, 32)
    dim3 gPV(1, S_ / 128, BH_);                // (1, 16, 32)

    k_zero<<<(N_ * D_) / 256, blk>>>();

    // ---- self attention ----
    k_gemm_bias<<<gProj, blk>>>(x, sa_wq, sa_bq, pq, N_, D_, D_, D_, D_, D_);
    k_gemm_bias<<<gProj, blk>>>(x, sa_wk, sa_bk, pk, N_, D_, D_, D_, D_, D_);
    k_gemm_bias<<<gProj, blk>>>(x, sa_wv, sa_bv, pv, N_, D_, D_, D_, D_, D_);
    k_scores<<<gScores, blk>>>();
    k_softmax<<<BH_ * S_, blk>>>();
    k_pv<<<gPV, blk>>>();
    k_gemm_bias<<<gProj, blk>>>(pattn, sa_wo, sa_bo, pt, N_, D_, D_, D_, D_, D_);
    k_addln<<<N_, blk>>>(x, pt, n1_g, n1_b, px1);

    // ---- cross attention ----
    k_gemm_bias<<<gProj, blk>>>(px1, ca_wq, ca_bq, pq, N_, D_, D_, D_, D_, D_);
    k_gemm_bias<<<gProj, blk>>>(enc, ca_wk, ca_bk, pk, N_, D_, D_, D_, D_, D_);
    k_gemm_bias<<<gProj, blk>>>(enc, ca_wv, ca_bv, pv, N_, D_, D_, D_, D_, D_);
    k_scores<<<gScores, blk>>>();
    k_softmax<<<BH_ * S_, blk>>>();
    k_pv<<<gPV, blk>>>();
    k_gemm_bias<<<gProj, blk>>>(pattn, ca_wo, ca_bo, pt, N_, D_, D_, D_, D_, D_);
    k_addln<<<N_, blk>>>(px1, pt, n2_g, n2_b, px2);

    // ---- MoE (sparse top-2 dispatch) ----
    k_router<<<N_ / 8, blk>>>(r_w, r_b);
    k_scan<<<1, 32>>>();
    k_fill<<<N_ / 256, blk>>>();
    k_ff1<<<dim3(F_ / 128, N_ / 128, E_), blk>>>(e_w1, e_b1);
    k_ff2<<<dim3(D_ / 128, N_ / 128, E_), blk>>>(e_w2, e_b2);
    k_addln<<<N_, blk>>>(px2, pmoe, n3_g, n3_b, out);

    // ---- aux loss on final output ----
    k_aux_router<<<N_ / 8, blk>>>(out, r_w, r_b);
    k_aux_reduce<<<1, blk>>>(out, ((long)out_size > ND_) ? 1 : 0);
}

// round 2
// speedup vs baseline: 2.0137x; 2.0137x over previous
#include <cuda_runtime.h>
#include <math.h>
#include <stdint.h>

#define D_  1024
#define H_  16
#define DH_ 64
#define F_  4096
#define E_  8
#define K_  2
#define B_  2
#define S_  2048
#define N_  (B_ * S_)          // 4096 tokens
#define BH_ (B_ * H_)          // 32
#define ND_ ((long)N_ * D_)    // 4194304

// ---------------- scratch (device globals; no allocation allowed) -------------
__device__ float g_q[N_ * D_];
__device__ float g_k[N_ * D_];
__device__ float g_v[N_ * D_];
__device__ float g_attn[N_ * D_];
__device__ float g_t[N_ * D_];
__device__ float g_x1[N_ * D_];
__device__ float g_x2[N_ * D_];
__device__ float g_moe[N_ * D_];
// big scratch: attention probabilities (32 * 2048 * 2048 floats = 512MB),
// later reused as the MoE hidden activations (8192 * 4096 floats = 128MB).
__device__ float g_s[(long)BH_ * S_ * S_];

__device__ int   g_topi[N_ * K_];
__device__ float g_gate[N_ * K_];
__device__ int   g_cnt[E_];
__device__ int   g_off[E_];
__device__ int   g_cur[E_];
__device__ int   g_dtok[N_ * K_];
__device__ float g_dgate[N_ * K_];
__device__ float g_probs[N_ * E_];
__device__ int   g_loadcnt[E_];

// ---------------- tf32 helpers ------------------------------------------------
__device__ __forceinline__ uint32_t f2t(float x)
{
    uint32_t u;
    asm("cvt.rna.tf32.f32 %0, %1;" : "=r"(u) : "f"(x));
    return u;
}

__device__ __forceinline__ void mma_tf32(float* c, const uint32_t* a, const uint32_t* b)
{
    asm volatile(
        "mma.sync.aligned.m16n8k8.row.col.f32.tf32.tf32.f32 "
        "{%0,%1,%2,%3}, {%4,%5,%6,%7}, {%8,%9}, {%0,%1,%2,%3};\n"
        : "+f"(c[0]), "+f"(c[1]), "+f"(c[2]), "+f"(c[3])
        : "r"(a[0]), "r"(a[1]), "r"(a[2]), "r"(a[3]), "r"(b[0]), "r"(b[1]));
}

// ---------------- generic tiled tf32 tensor-core GEMM core --------------------
// Block tile: 128 x BN, K-step 16, 256 threads (8 warps).
// BN=128: warp grid 2Mx4N, warp tile 64x32 (MI=4, NI=4)
// BN=64 : warp grid 4Mx2N, warp tile 32x32 (MI=2, NI=4)
#define TBM 128
#define TBK 16

template<int BN, bool TRANSB, bool GATHER, bool RELU, bool SCATTER>
__device__ __forceinline__ void gemm_block(
    const float* __restrict__ A, int lda,
    const float* __restrict__ B, int ldb,
    float* __restrict__ C, int ldc,
    int M, int N, int K,
    const float* __restrict__ bias,
    const int* __restrict__ gidx,      // gather rows for A (GATHER)
    const int* __restrict__ sidx,      // scatter rows for C (SCATTER)
    const float* __restrict__ rscale)  // per-row scale (SCATTER)
{
    // pad so row stride % 32 == 8 -> the (tig*stride + gid) fragment loads
    // hit 32 distinct banks (conflict-free LDS)
    __shared__ uint32_t As[TBK][TBM + 8];
    __shared__ uint32_t Bs[TBK][BN + 8];

    const int tid = threadIdx.x;
    const int m0 = blockIdx.y * TBM;
    const int n0 = blockIdx.x * BN;
    if (m0 >= M) return;

    constexpr int WMW = (BN == 128) ? 2 : 4;   // warps in M
    constexpr int WTM = TBM / WMW;             // 64 or 32
    constexpr int WTN = BN / (8 / WMW);        // 32
    constexpr int MI = WTM / 16;               // 4 or 2
    constexpr int NI = WTN / 8;                // 4

    const int w = tid >> 5;
    const int lane = tid & 31;
    const int gid = lane >> 2;                 // 0..7
    const int tig = lane & 3;                  // 0..3
    const int wm = (w % WMW) * WTM;
    const int wn = (w / WMW) * WTN;

    float acc[MI][NI][4];
#pragma unroll
    for (int mi = 0; mi < MI; mi++)
#pragma unroll
        for (int ni = 0; ni < NI; ni++)
#pragma unroll
            for (int r = 0; r < 4; r++) acc[mi][ni][r] = 0.f;

    // A loader: 128 rows x 16 cols, 8 floats/thread
    const int ar = tid >> 1;
    const int ac = (tid & 1) * 8;
    const bool avalid = (m0 + ar) < M;
    const float* Ap = A;
    if (avalid) {
        long grow = GATHER ? (long)gidx[m0 + ar] : (long)(m0 + ar);
        Ap = A + grow * (long)lda + ac;
    }

    constexpr int CPT = BN / 16;  // B floats per thread (8 or 4)

    for (int k0 = 0; k0 < K; k0 += TBK) {
        // ---- load A tile (transposed into smem, fp32 -> tf32) ----
        if (avalid) {
            float4 a0 = *(const float4*)(Ap + k0);
            float4 a1 = *(const float4*)(Ap + k0 + 4);
            As[ac + 0][ar] = f2t(a0.x); As[ac + 1][ar] = f2t(a0.y);
            As[ac + 2][ar] = f2t(a0.z); As[ac + 3][ar] = f2t(a0.w);
            As[ac + 4][ar] = f2t(a1.x); As[ac + 5][ar] = f2t(a1.y);
            As[ac + 6][ar] = f2t(a1.z); As[ac + 7][ar] = f2t(a1.w);
        } else {
#pragma unroll
            for (int i = 0; i < 8; i++) As[ac + i][ar] = 0;
        }
        // ---- load B tile ----
        if constexpr (TRANSB) {
            // logical B[k][n] stored as Bphys[n][k]; tile = BN n-rows x 16 k-cols
            constexpr int TPR = 16 / CPT;           // threads per n-row
            const int brow = tid / TPR;
            const int bc = (tid % TPR) * CPT;
            const float* bp = B + (long)(n0 + brow) * ldb + k0 + bc;
#pragma unroll
            for (int v = 0; v < CPT; v += 4) {
                float4 b4 = *(const float4*)(bp + v);
                Bs[bc + v + 0][brow] = f2t(b4.x);
                Bs[bc + v + 1][brow] = f2t(b4.y);
                Bs[bc + v + 2][brow] = f2t(b4.z);
                Bs[bc + v + 3][brow] = f2t(b4.w);
            }
        } else {
            const int br = tid >> 4;
            const int bc = (tid & 15) * CPT;
            const float* bp = B + (long)(k0 + br) * ldb + n0 + bc;
#pragma unroll
            for (int v = 0; v < CPT; v += 4) {
                float4 b4 = *(const float4*)(bp + v);
                Bs[br][bc + v + 0] = f2t(b4.x);
                Bs[br][bc + v + 1] = f2t(b4.y);
                Bs[br][bc + v + 2] = f2t(b4.z);
                Bs[br][bc + v + 3] = f2t(b4.w);
            }
        }
        __syncthreads();
        // ---- tensor-core compute: 2 k-subtiles of 8 ----
#pragma unroll
        for (int ks = 0; ks < TBK; ks += 8) {
            uint32_t af[MI][4], bf[NI][2];
#pragma unroll
            for (int mi = 0; mi < MI; mi++) {
                const int mrow = wm + mi * 16 + gid;
                af[mi][0] = As[ks + tig][mrow];
                af[mi][1] = As[ks + tig][mrow + 8];
                af[mi][2] = As[ks + tig + 4][mrow];
                af[mi][3] = As[ks + tig + 4][mrow + 8];
            }
#pragma unroll
            for (int ni = 0; ni < NI; ni++) {
                const int ncol = wn + ni * 8 + gid;
                bf[ni][0] = Bs[ks + tig][ncol];
                bf[ni][1] = Bs[ks + tig + 4][ncol];
            }
#pragma unroll
            for (int mi = 0; mi < MI; mi++)
#pragma unroll
                for (int ni = 0; ni < NI; ni++)
                    mma_tf32(acc[mi][ni], af[mi], bf[ni]);
        }
        __syncthreads();
    }

    // ---- epilogue ----
    // c0:(row, col) c1:(row, col+1) c2:(row+8, col) c3:(row+8, col+1)
#pragma unroll
    for (int mi = 0; mi < MI; mi++) {
#pragma unroll
        for (int half = 0; half < 2; half++) {
            const int row = m0 + wm + mi * 16 + gid + half * 8;
            if (row >= M) continue;
            float sc = 1.f;
            long crow = row;
            if constexpr (SCATTER) { sc = rscale[row]; crow = sidx[row]; }
            float* cp = C + crow * (long)ldc;
#pragma unroll
            for (int ni = 0; ni < NI; ni++) {
                const int col = n0 + wn + ni * 8 + tig * 2;
                float v0 = acc[mi][ni][half * 2 + 0];
                float v1 = acc[mi][ni][half * 2 + 1];
                if (bias) { v0 += bias[col]; v1 += bias[col + 1]; }
                if constexpr (RELU) { v0 = fmaxf(v0, 0.f); v1 = fmaxf(v1, 0.f); }
                if constexpr (SCATTER) {
                    atomicAdd(cp + col, v0 * sc);
                    atomicAdd(cp + col + 1, v1 * sc);
                } else {
                    *(float2*)(cp + col) = make_float2(v0, v1);
                }
            }
        }
    }
}

// ---------------- GEMM kernel wrappers ----------------------------------------
__global__ void __launch_bounds__(256) k_gemm_bias(
    const float* __restrict__ A, const float* __restrict__ B,
    const float* __restrict__ bias, float* __restrict__ C,
    int M, int N, int K, int lda, int ldb, int ldc)
{
    gemm_block<128, false, false, false, false>(A, lda, B, ldb, C, ldc,
                                                M, N, K, bias,
                                                nullptr, nullptr, nullptr);
}

// scores[z] = Q_z @ K_z^T   (z = b*H + h), NT layout
__global__ void __launch_bounds__(256) k_scores()
{
    const int z = blockIdx.z, b = z >> 4, h = z & 15;
    const float* A = g_q + (long)b * S_ * D_ + h * DH_;
    const float* B = g_k + (long)b * S_ * D_ + h * DH_;
    float* C = g_s + (long)z * S_ * S_;
    gemm_block<128, true, false, false, false>(A, D_, B, D_, C, S_,
                                               S_, S_, DH_, nullptr,
                                               nullptr, nullptr, nullptr);
}

// attn[z] = P_z @ V_z  (N = 64, narrow tile)
__global__ void __launch_bounds__(256) k_pv()
{
    const int z = blockIdx.z, b = z >> 4, h = z & 15;
    const float* A = g_s + (long)z * S_ * S_;
    const float* B = g_v + (long)b * S_ * D_ + h * DH_;
    float* C = g_attn + (long)b * S_ * D_ + h * DH_;
    gemm_block<64, false, false, false, false>(A, S_, B, D_, C, D_,
                                               S_, DH_, S_, nullptr,
                                               nullptr, nullptr, nullptr);
}

// MoE FF1: h = relu(gather(x2) @ W1[e] + b1[e]) into g_s (reused as hidden buf)
__global__ void __launch_bounds__(256) k_ff1(
    const float* __restrict__ W1, const float* __restrict__ B1)
{
    const int e = blockIdx.z;
    const int cnt = g_cnt[e];
    if ((int)(blockIdx.y * TBM) >= cnt) return;
    const int off = g_off[e];
    gemm_block<128, false, true, true, false>(
        g_x2, D_, W1 + (long)e * D_ * F_, F_,
        g_s + (long)off * F_, F_,
        cnt, F_, D_, B1 + (long)e * F_,
        g_dtok + off, nullptr, nullptr);
}

// MoE FF2: moe_out[tok] += gate * (h @ W2[e] + b2[e])   (atomic scatter)
__global__ void __launch_bounds__(256) k_ff2(
    const float* __restrict__ W2, const float* __restrict__ B2)
{
    const int e = blockIdx.z;
    const int cnt = g_cnt[e];
    if ((int)(blockIdx.y * TBM) >= cnt) return;
    const int off = g_off[e];
    gemm_block<128, false, false, false, true>(
        g_s + (long)off * F_, F_, W2 + (long)e * F_ * D_, D_,
        g_moe, D_, cnt, D_, F_, B2 + (long)e * D_,
        nullptr, g_dtok + off, g_dgate + off);
}

// ---------------- elementwise / softmax / LN ----------------------------------
__global__ void k_zero()
{
    long i = (long)blockIdx.x * 256 + threadIdx.x;
    if (i < ND_) g_moe[i] = 0.f;
    if (i < E_) { g_cnt[i] = 0; g_cur[i] = 0; g_loadcnt[i] = 0; }
}

// row softmax of scores with 1/sqrt(DH) scale applied inside the exp
__global__ void k_softmax()
{
    __shared__ float buf[S_];
    __shared__ float red[256];
    const long row = blockIdx.x;
    float* p = g_s + row * (long)S_;
    const int tid = threadIdx.x;
    float mx = -3.4e38f;
    for (int i = tid; i < S_; i += 256) { float v = p[i]; buf[i] = v; mx = fmaxf(mx, v); }
    red[tid] = mx; __syncthreads();
    for (int o = 128; o > 0; o >>= 1) { if (tid < o) red[tid] = fmaxf(red[tid], red[tid + o]); __syncthreads(); }
    mx = red[0]; __syncthreads();
    float sum = 0.f;
    for (int i = tid; i < S_; i += 256) { float e = expf((buf[i] - mx) * 0.125f); buf[i] = e; sum += e; }
    red[tid] = sum; __syncthreads();
    for (int o = 128; o > 0; o >>= 1) { if (tid < o) red[tid] += red[tid + o]; __syncthreads(); }
    float inv = 1.f / red[0];
    for (int i = tid; i < S_; i += 256) p[i] = buf[i] * inv;
}

// out = LayerNorm(a + b) * g + beta, one block per token
__global__ void k_addln(const float* __restrict__ a, const float* __restrict__ b,
                        const float* __restrict__ g, const float* __restrict__ be,
                        float* __restrict__ out)
{
    __shared__ float buf[D_];
    __shared__ float red[256];
    const int t = blockIdx.x;
    const int tid = threadIdx.x;
    const float* pa = a + (long)t * D_;
    const float* pb = b + (long)t * D_;
    float s = 0.f;
    for (int i = tid; i < D_; i += 256) { float v = pa[i] + pb[i]; buf[i] = v; s += v; }
    red[tid] = s; __syncthreads();
    for (int o = 128; o > 0; o >>= 1) { if (tid < o) red[tid] += red[tid + o]; __syncthreads(); }
    float mean = red[0] * (1.f / D_);
    __syncthreads();
    float vs = 0.f;
    for (int i = tid; i < D_; i += 256) { float d = buf[i] - mean; vs += d * d; }
    red[tid] = vs; __syncthreads();
    for (int o = 128; o > 0; o >>= 1) { if (tid < o) red[tid] += red[tid + o]; __syncthreads(); }
    float rstd = rsqrtf(red[0] * (1.f / D_) + 1e-5f);
    float* po = out + (long)t * D_;
    for (int i = tid; i < D_; i += 256)
        po[i] = (buf[i] - mean) * rstd * g[i] + be[i];
}

// ---------------- router / dispatch / aux --------------------------------------
// One warp per token: logits = x @ r_w + r_b, softmax over 8, top-2 w/ lowest-
// index tiebreak (matches jax.lax.top_k).
__device__ __forceinline__ void router_core(const float* __restrict__ x,
                                            const float* __restrict__ rw,
                                            const float* __restrict__ rb,
                                            int lane, float* probs_out,
                                            int* i1_out, int* i2_out)
{
    float le[E_];
#pragma unroll
    for (int e = 0; e < E_; e++) le[e] = 0.f;
    for (int d0 = lane * 4; d0 < D_; d0 += 128) {
        float4 xv = *(const float4*)(x + d0);
        float xa[4] = {xv.x, xv.y, xv.z, xv.w};
#pragma unroll
        for (int r = 0; r < 4; r++) {
            const float* w = rw + (long)(d0 + r) * E_;
            float4 w0 = *(const float4*)(w);
            float4 w1 = *(const float4*)(w + 4);
            le[0] = fmaf(xa[r], w0.x, le[0]); le[1] = fmaf(xa[r], w0.y, le[1]);
            le[2] = fmaf(xa[r], w0.z, le[2]); le[3] = fmaf(xa[r], w0.w, le[3]);
            le[4] = fmaf(xa[r], w1.x, le[4]); le[5] = fmaf(xa[r], w1.y, le[5]);
            le[6] = fmaf(xa[r], w1.z, le[6]); le[7] = fmaf(xa[r], w1.w, le[7]);
        }
    }
#pragma unroll
    for (int e = 0; e < E_; e++)
        for (int o = 16; o > 0; o >>= 1) le[e] += __shfl_xor_sync(0xffffffffu, le[e], o);
    float mx = -3.4e38f;
#pragma unroll
    for (int e = 0; e < E_; e++) { le[e] += rb[e]; mx = fmaxf(mx, le[e]); }
    float sum = 0.f;
#pragma unroll
    for (int e = 0; e < E_; e++) { le[e] = expf(le[e] - mx); sum += le[e]; }
    float inv = 1.f / sum;
#pragma unroll
    for (int e = 0; e < E_; e++) { le[e] *= inv; probs_out[e] = le[e]; }
    int i1 = 0;
    for (int e = 1; e < E_; e++) if (le[e] > le[i1]) i1 = e;
    int i2 = (i1 == 0) ? 1 : 0;
    for (int e = 0; e < E_; e++) if (e != i1 && le[e] > le[i2]) i2 = e;
    *i1_out = i1; *i2_out = i2;
}

__global__ void k_router(const float* __restrict__ rw, const float* __restrict__ rb)
{
    const int warp = threadIdx.x >> 5, lane = threadIdx.x & 31;
    const int t = blockIdx.x * 8 + warp;
    if (t >= N_) return;
    float probs[E_]; int i1, i2;
    router_core(g_x2 + (long)t * D_, rw, rb, lane, probs, &i1, &i2);
    if (lane == 0) {
        float gs = probs[i1] + probs[i2];
        g_topi[t * 2] = i1; g_topi[t * 2 + 1] = i2;
        g_gate[t * 2] = probs[i1] / gs; g_gate[t * 2 + 1] = probs[i2] / gs;
        atomicAdd(&g_cnt[i1], 1); atomicAdd(&g_cnt[i2], 1);
    }
}

__global__ void k_scan()
{
    if (threadIdx.x == 0) {
        int s = 0;
        for (int e = 0; e < E_; e++) { g_off[e] = s; s += g_cnt[e]; }
    }
}

__global__ void k_fill()
{
    int t = blockIdx.x * 256 + threadIdx.x;
    if (t >= N_) return;
#pragma unroll
    for (int k = 0; k < K_; k++) {
        int e = g_topi[t * K_ + k];
        int p = atomicAdd(&g_cur[e], 1);
        int d = g_off[e] + p;
        g_dtok[d] = t;
        g_dgate[d] = g_gate[t * K_ + k];
    }
}

// aux-loss router pass on the FINAL output
__global__ void k_aux_router(const float* __restrict__ X,
                             const float* __restrict__ rw, const float* __restrict__ rb)
{
    const int warp = threadIdx.x >> 5, lane = threadIdx.x & 31;
    const int t = blockIdx.x * 8 + warp;
    if (t >= N_) return;
    float probs[E_]; int i1, i2;
    router_core(X + (long)t * D_, rw, rb, lane, probs, &i1, &i2);
    if (lane == 0) {
#pragma unroll
        for (int e = 0; e < E_; e++) g_probs[t * E_ + e] = probs[e];
        atomicAdd(&g_loadcnt[i1], 1); atomicAdd(&g_loadcnt[i2], 1);
    }
}

// deterministic fixed-order reduction of importance; aux -> out[N*D]
__global__ void k_aux_reduce(float* __restrict__ out, int write)
{
    __shared__ float red[256];
    const int tid = threadIdx.x;
    float imp[E_];
#pragma unroll
    for (int e = 0; e < E_; e++) imp[e] = 0.f;
    for (int t = tid; t < N_; t += 256)
#pragma unroll
        for (int e = 0; e < E_; e++) imp[e] += g_probs[t * E_ + e];
    float aux = 0.f;
    for (int e = 0; e < E_; e++) {
        red[tid] = imp[e]; __syncthreads();
        for (int o = 128; o > 0; o >>= 1) { if (tid < o) red[tid] += red[tid + o]; __syncthreads(); }
        if (tid == 0)
            aux += (red[0] / (float)N_) * ((float)g_loadcnt[e] / (float)(N_ * K_));
        __syncthreads();
    }
    if (tid == 0 && write) out[ND_] = aux * (float)E_;
}

// ---------------- launch ------------------------------------------------------
extern "C" void kernel_launch(void* const* d_in, const int* in_sizes, int n_in,
                              void* d_out, int out_size)
{
    (void)in_sizes; (void)n_in;
    const float* x     = (const float*)d_in[0];
    const float* enc   = (const float*)d_in[1];
    const float* sa_wq = (const float*)d_in[2];
    const float* sa_bq = (const float*)d_in[3];
    const float* sa_wk = (const float*)d_in[4];
    const float* sa_bk = (const float*)d_in[5];
    const float* sa_wv = (const float*)d_in[6];
    const float* sa_bv = (const float*)d_in[7];
    const float* sa_wo = (const float*)d_in[8];
    const float* sa_bo = (const float*)d_in[9];
    const float* ca_wq = (const float*)d_in[10];
    const float* ca_bq = (const float*)d_in[11];
    const float* ca_wk = (const float*)d_in[12];
    const float* ca_bk = (const float*)d_in[13];
    const float* ca_wv = (const float*)d_in[14];
    const float* ca_bv = (const float*)d_in[15];
    const float* ca_wo = (const float*)d_in[16];
    const float* ca_bo = (const float*)d_in[17];
    const float* n1_g  = (const float*)d_in[18];
    const float* n1_b  = (const float*)d_in[19];
    const float* n2_g  = (const float*)d_in[20];
    const float* n2_b  = (const float*)d_in[21];
    const float* n3_g  = (const float*)d_in[22];
    const float* n3_b  = (const float*)d_in[23];
    const float* r_w   = (const float*)d_in[24];
    const float* r_b   = (const float*)d_in[25];
    const float* e_w1  = (const float*)d_in[26];
    const float* e_b1  = (const float*)d_in[27];
    const float* e_w2  = (const float*)d_in[28];
    const float* e_b2  = (const float*)d_in[29];
    float* out = (float*)d_out;

    float *pq, *pk, *pv, *pattn, *pt, *px1, *px2, *pmoe;
    cudaGetSymbolAddress((void**)&pq, g_q);
    cudaGetSymbolAddress((void**)&pk, g_k);
    cudaGetSymbolAddress((void**)&pv, g_v);
    cudaGetSymbolAddress((void**)&pattn, g_attn);
    cudaGetSymbolAddress((void**)&pt, g_t);
    cudaGetSymbolAddress((void**)&px1, g_x1);
    cudaGetSymbolAddress((void**)&px2, g_x2);
    cudaGetSymbolAddress((void**)&pmoe, g_moe);

    dim3 blk(256);
    dim3 gProj(D_ / 128, N_ / 128);            // (8, 32)
    dim3 gScores(S_ / 128, S_ / 128, BH_);     // (16, 16, 32)
    dim3 gPV(1, S_ / 128, BH_);                // (1, 16, 32)

    k_zero<<<(N_ * D_) / 256, blk>>>();

    // ---- self attention ----
    k_gemm_bias<<<gProj, blk>>>(x, sa_wq, sa_bq, pq, N_, D_, D_, D_, D_, D_);
    k_gemm_bias<<<gProj, blk>>>(x, sa_wk, sa_bk, pk, N_, D_, D_, D_, D_, D_);
    k_gemm_bias<<<gProj, blk>>>(x, sa_wv, sa_bv, pv, N_, D_, D_, D_, D_, D_);
    k_scores<<<gScores, blk>>>();
    k_softmax<<<BH_ * S_, blk>>>();
    k_pv<<<gPV, blk>>>();
    k_gemm_bias<<<gProj, blk>>>(pattn, sa_wo, sa_bo, pt, N_, D_, D_, D_, D_, D_);
    k_addln<<<N_, blk>>>(x, pt, n1_g, n1_b, px1);

    // ---- cross attention ----
    k_gemm_bias<<<gProj, blk>>>(px1, ca_wq, ca_bq, pq, N_, D_, D_, D_, D_, D_);
    k_gemm_bias<<<gProj, blk>>>(enc, ca_wk, ca_bk, pk, N_, D_, D_, D_, D_, D_);
    k_gemm_bias<<<gProj, blk>>>(enc, ca_wv, ca_bv, pv, N_, D_, D_, D_, D_, D_);
    k_scores<<<gScores, blk>>>();
    k_softmax<<<BH_ * S_, blk>>>();
    k_pv<<<gPV, blk>>>();
    k_gemm_bias<<<gProj, blk>>>(pattn, ca_wo, ca_bo, pt, N_, D_, D_, D_, D_, D_);
    k_addln<<<N_, blk>>>(px1, pt, n2_g, n2_b, px2);

    // ---- MoE (sparse top-2 dispatch) ----
    k_router<<<N_ / 8, blk>>>(r_w, r_b);
    k_scan<<<1, 32>>>();
    k_fill<<<N_ / 256, blk>>>();
    k_ff1<<<dim3(F_ / 128, N_ / 128, E_), blk>>>(e_w1, e_b1);
    k_ff2<<<dim3(D_ / 128, N_ / 128, E_), blk>>>(e_w2, e_b2);
    k_addln<<<N_, blk>>>(px2, pmoe, n3_g, n3_b, out);

    // ---- aux loss on final output ----
    k_aux_router<<<N_ / 8, blk>>>(out, r_w, r_b);
    k_aux_reduce<<<1, blk>>>(out, ((long)out_size > ND_) ? 1 : 0);
}

// round 3
// speedup vs baseline: 2.4165x; 1.2000x over previous
#include <cuda_runtime.h>
#include <math.h>
#include <stdint.h>

#define D_  1024
#define H_  16
#define DH_ 64
#define F_  4096
#define E_  8
#define K_  2
#define B_  2
#define S_  2048
#define N_  (B_ * S_)          // 4096 tokens
#define BH_ (B_ * H_)          // 32
#define ND_ ((long)N_ * D_)    // 4194304

// ---------------- scratch (device globals; no allocation allowed) -------------
__device__ float g_q[N_ * D_];
__device__ float g_k[N_ * D_];
__device__ float g_v[N_ * D_];
__device__ float g_attn[N_ * D_];
__device__ float g_t[N_ * D_];
__device__ float g_x1[N_ * D_];
__device__ float g_x2[N_ * D_];
__device__ float g_moe[N_ * D_];
// MoE hidden activations (8192 * 4096 floats = 128MB)
__device__ float g_s[(long)N_ * K_ * F_];

__device__ int   g_topi[N_ * K_];
__device__ float g_gate[N_ * K_];
__device__ int   g_cnt[E_];
__device__ int   g_off[E_];
__device__ int   g_cur[E_];
__device__ int   g_dtok[N_ * K_];
__device__ float g_dgate[N_ * K_];
__device__ float g_probs[N_ * E_];
__device__ int   g_loadcnt[E_];

// ---------------- tf32 helpers ------------------------------------------------
__device__ __forceinline__ uint32_t f2t(float x)
{
    uint32_t u;
    asm("cvt.rna.tf32.f32 %0, %1;" : "=r"(u) : "f"(x));
    return u;
}

__device__ __forceinline__ void mma_tf32(float* c, const uint32_t* a, const uint32_t* b)
{
    asm volatile(
        "mma.sync.aligned.m16n8k8.row.col.f32.tf32.tf32.f32 "
        "{%0,%1,%2,%3}, {%4,%5,%6,%7}, {%8,%9}, {%0,%1,%2,%3};\n"
        : "+f"(c[0]), "+f"(c[1]), "+f"(c[2]), "+f"(c[3])
        : "r"(a[0]), "r"(a[1]), "r"(a[2]), "r"(a[3]), "r"(b[0]), "r"(b[1]));
}

// ---------------- generic tiled tf32 tensor-core GEMM core --------------------
// Block tile: 128 x BN, K-step 16, 256 threads (8 warps).
#define TBM 128
#define TBK 16

template<int BN, bool TRANSB, bool GATHER, bool RELU, bool SCATTER>
__device__ __forceinline__ void gemm_block(
    const float* __restrict__ A, int lda,
    const float* __restrict__ B, int ldb,
    float* __restrict__ C, int ldc,
    int M, int N, int K,
    const float* __restrict__ bias,
    const int* __restrict__ gidx,
    const int* __restrict__ sidx,
    const float* __restrict__ rscale)
{
    __shared__ uint32_t As[TBK][TBM + 8];
    __shared__ uint32_t Bs[TBK][BN + 8];

    const int tid = threadIdx.x;
    const int m0 = blockIdx.y * TBM;
    const int n0 = blockIdx.x * BN;
    if (m0 >= M) return;

    constexpr int WMW = (BN == 128) ? 2 : 4;
    constexpr int WTM = TBM / WMW;
    constexpr int WTN = BN / (8 / WMW);
    constexpr int MI = WTM / 16;
    constexpr int NI = WTN / 8;

    const int w = tid >> 5;
    const int lane = tid & 31;
    const int gid = lane >> 2;
    const int tig = lane & 3;
    const int wm = (w % WMW) * WTM;
    const int wn = (w / WMW) * WTN;

    float acc[MI][NI][4];
#pragma unroll
    for (int mi = 0; mi < MI; mi++)
#pragma unroll
        for (int ni = 0; ni < NI; ni++)
#pragma unroll
            for (int r = 0; r < 4; r++) acc[mi][ni][r] = 0.f;

    const int ar = tid >> 1;
    const int ac = (tid & 1) * 8;
    const bool avalid = (m0 + ar) < M;
    const float* Ap = A;
    if (avalid) {
        long grow = GATHER ? (long)gidx[m0 + ar] : (long)(m0 + ar);
        Ap = A + grow * (long)lda + ac;
    }

    constexpr int CPT = BN / 16;

    for (int k0 = 0; k0 < K; k0 += TBK) {
        if (avalid) {
            float4 a0 = *(const float4*)(Ap + k0);
            float4 a1 = *(const float4*)(Ap + k0 + 4);
            As[ac + 0][ar] = f2t(a0.x); As[ac + 1][ar] = f2t(a0.y);
            As[ac + 2][ar] = f2t(a0.z); As[ac + 3][ar] = f2t(a0.w);
            As[ac + 4][ar] = f2t(a1.x); As[ac + 5][ar] = f2t(a1.y);
            As[ac + 6][ar] = f2t(a1.z); As[ac + 7][ar] = f2t(a1.w);
        } else {
#pragma unroll
            for (int i = 0; i < 8; i++) As[ac + i][ar] = 0;
        }
        if constexpr (TRANSB) {
            constexpr int TPR = 16 / CPT;
            const int brow = tid / TPR;
            const int bc = (tid % TPR) * CPT;
            const float* bp = B + (long)(n0 + brow) * ldb + k0 + bc;
#pragma unroll
            for (int v = 0; v < CPT; v += 4) {
                float4 b4 = *(const float4*)(bp + v);
                Bs[bc + v + 0][brow] = f2t(b4.x);
                Bs[bc + v + 1][brow] = f2t(b4.y);
                Bs[bc + v + 2][brow] = f2t(b4.z);
                Bs[bc + v + 3][brow] = f2t(b4.w);
            }
        } else {
            const int br = tid >> 4;
            const int bc = (tid & 15) * CPT;
            const float* bp = B + (long)(k0 + br) * ldb + n0 + bc;
#pragma unroll
            for (int v = 0; v < CPT; v += 4) {
                float4 b4 = *(const float4*)(bp + v);
                Bs[br][bc + v + 0] = f2t(b4.x);
                Bs[br][bc + v + 1] = f2t(b4.y);
                Bs[br][bc + v + 2] = f2t(b4.z);
                Bs[br][bc + v + 3] = f2t(b4.w);
            }
        }
        __syncthreads();
#pragma unroll
        for (int ks = 0; ks < TBK; ks += 8) {
            uint32_t af[MI][4], bf[NI][2];
#pragma unroll
            for (int mi = 0; mi < MI; mi++) {
                const int mrow = wm + mi * 16 + gid;
                af[mi][0] = As[ks + tig][mrow];
                af[mi][1] = As[ks + tig][mrow + 8];
                af[mi][2] = As[ks + tig + 4][mrow];
                af[mi][3] = As[ks + tig + 4][mrow + 8];
            }
#pragma unroll
            for (int ni = 0; ni < NI; ni++) {
                const int ncol = wn + ni * 8 + gid;
                bf[ni][0] = Bs[ks + tig][ncol];
                bf[ni][1] = Bs[ks + tig + 4][ncol];
            }
#pragma unroll
            for (int mi = 0; mi < MI; mi++)
#pragma unroll
                for (int ni = 0; ni < NI; ni++)
                    mma_tf32(acc[mi][ni], af[mi], bf[ni]);
        }
        __syncthreads();
    }

#pragma unroll
    for (int mi = 0; mi < MI; mi++) {
#pragma unroll
        for (int half = 0; half < 2; half++) {
            const int row = m0 + wm + mi * 16 + gid + half * 8;
            if (row >= M) continue;
            float sc = 1.f;
            long crow = row;
            if constexpr (SCATTER) { sc = rscale[row]; crow = sidx[row]; }
            float* cp = C + crow * (long)ldc;
#pragma unroll
            for (int ni = 0; ni < NI; ni++) {
                const int col = n0 + wn + ni * 8 + tig * 2;
                float v0 = acc[mi][ni][half * 2 + 0];
                float v1 = acc[mi][ni][half * 2 + 1];
                if (bias) { v0 += bias[col]; v1 += bias[col + 1]; }
                if constexpr (RELU) { v0 = fmaxf(v0, 0.f); v1 = fmaxf(v1, 0.f); }
                if constexpr (SCATTER) {
                    atomicAdd(cp + col, v0 * sc);
                    atomicAdd(cp + col + 1, v1 * sc);
                } else {
                    *(float2*)(cp + col) = make_float2(v0, v1);
                }
            }
        }
    }
}

// ---------------- GEMM kernel wrappers ----------------------------------------
// projections: BN=64 (more blocks -> better latency hiding / wave balance)
__global__ void __launch_bounds__(256) k_gemm64(
    const float* __restrict__ A, const float* __restrict__ B,
    const float* __restrict__ bias, float* __restrict__ C,
    int M, int N, int K, int lda, int ldb, int ldc)
{
    gemm_block<64, false, false, false, false>(A, lda, B, ldb, C, ldc,
                                               M, N, K, bias,
                                               nullptr, nullptr, nullptr);
}

// MoE FF1: h = relu(gather(x2) @ W1[e] + b1[e]) into g_s
__global__ void __launch_bounds__(256) k_ff1(
    const float* __restrict__ W1, const float* __restrict__ B1)
{
    const int e = blockIdx.z;
    const int cnt = g_cnt[e];
    if ((int)(blockIdx.y * TBM) >= cnt) return;
    const int off = g_off[e];
    gemm_block<128, false, true, true, false>(
        g_x2, D_, W1 + (long)e * D_ * F_, F_,
        g_s + (long)off * F_, F_,
        cnt, F_, D_, B1 + (long)e * F_,
        g_dtok + off, nullptr, nullptr);
}

// MoE FF2: moe_out[tok] += gate * (h @ W2[e] + b2[e])   (atomic scatter)
__global__ void __launch_bounds__(256) k_ff2(
    const float* __restrict__ W2, const float* __restrict__ B2)
{
    const int e = blockIdx.z;
    const int cnt = g_cnt[e];
    if ((int)(blockIdx.y * TBM) >= cnt) return;
    const int off = g_off[e];
    gemm_block<128, false, false, false, true>(
        g_s + (long)off * F_, F_, W2 + (long)e * F_ * D_, D_,
        g_moe, D_, cnt, D_, F_, B2 + (long)e * D_,
        nullptr, g_dtok + off, g_dgate + off);
}

// ---------------- flash attention ---------------------------------------------
// One block = one (batch,head) z and one 128-row query tile. 256 threads,
// 8 warps, each warp owns 16 query rows. K/V streamed in 64-row tiles with
// online softmax; P goes through per-warp-private smem to become tf32
// A-fragments; O accumulated in registers (fp32).
// smem word strides: Qs/Ps/Ks = 68 (=4 mod 32), Vs = 72 (=8 mod 32): all
// fragment LDS patterns hit 32 distinct banks.
#define QS_OFF 0
#define PS_OFF 8704
#define KS_OFF 17408
#define VS_OFF 21760
#define FL_SMEM_WORDS 26368   // *4 = 105472 bytes

__global__ void __launch_bounds__(256) k_flash()
{
    extern __shared__ uint32_t sm[];
#define QS(r, c) sm[QS_OFF + (r) * 68 + (c)]
#define PS(r, c) sm[PS_OFF + (r) * 68 + (c)]
#define KS(r, c) sm[KS_OFF + (r) * 68 + (c)]
#define VS(r, c) sm[VS_OFF + (r) * 72 + (c)]

    const int tid = threadIdx.x;
    const int w = tid >> 5;
    const int lane = tid & 31;
    const int gid = lane >> 2;
    const int tig = lane & 3;
    const int wm = w * 16;

    const int qb = blockIdx.x;
    const int z = blockIdx.y;
    const int b = z >> 4, h = z & 15;
    const int q0 = qb * 128;

    // ---- load Q tile (128 x 64), pre-scaled by 1/sqrt(DH)=0.125 ----
    {
        const int r = tid >> 1;
        const int c0 = (tid & 1) * 32;
        const float* qp = g_q + ((long)(b * S_ + q0 + r)) * D_ + h * DH_ + c0;
#pragma unroll
        for (int i = 0; i < 8; i++) {
            float4 qv = *(const float4*)(qp + i * 4);
            uint4 u;
            u.x = f2t(qv.x * 0.125f); u.y = f2t(qv.y * 0.125f);
            u.z = f2t(qv.z * 0.125f); u.w = f2t(qv.w * 0.125f);
            *(uint4*)&QS(r, c0 + i * 4) = u;
        }
    }

    float m0v = -3.4e38f, m1v = -3.4e38f;
    float l0 = 0.f, l1 = 0.f;
    float o[8][4];
#pragma unroll
    for (int ni = 0; ni < 8; ni++)
#pragma unroll
        for (int r = 0; r < 4; r++) o[ni][r] = 0.f;

    const int ls = tid >> 2;             // kv row this thread loads
    const int ld0 = (tid & 3) * 16;      // dh offset

    for (int j = 0; j < S_ / 64; j++) {
        // ---- load K/V tiles (64 x 64 each) ----
        {
            const long base = ((long)(b * S_ + j * 64 + ls)) * D_ + h * DH_ + ld0;
            const float* kp = g_k + base;
            const float* vp = g_v + base;
#pragma unroll
            for (int i = 0; i < 4; i++) {
                float4 kv = *(const float4*)(kp + i * 4);
                uint4 u;
                u.x = f2t(kv.x); u.y = f2t(kv.y); u.z = f2t(kv.z); u.w = f2t(kv.w);
                *(uint4*)&KS(ls, ld0 + i * 4) = u;
                float4 vv = *(const float4*)(vp + i * 4);
                uint4 v;
                v.x = f2t(vv.x); v.y = f2t(vv.y); v.z = f2t(vv.z); v.w = f2t(vv.w);
                *(uint4*)&VS(ls, ld0 + i * 4) = v;
            }
        }
        __syncthreads();

        // ---- S = Q @ K^T  (warp: 16 rows x 64 keys) ----
        float sacc[8][4];
#pragma unroll
        for (int ni = 0; ni < 8; ni++)
#pragma unroll
            for (int r = 0; r < 4; r++) sacc[ni][r] = 0.f;
#pragma unroll
        for (int ks = 0; ks < 64; ks += 8) {
            uint32_t af[4];
            af[0] = QS(wm + gid, ks + tig);
            af[1] = QS(wm + gid + 8, ks + tig);
            af[2] = QS(wm + gid, ks + tig + 4);
            af[3] = QS(wm + gid + 8, ks + tig + 4);
#pragma unroll
            for (int ni = 0; ni < 8; ni++) {
                uint32_t bf[2];
                bf[0] = KS(ni * 8 + gid, ks + tig);
                bf[1] = KS(ni * 8 + gid, ks + tig + 4);
                mma_tf32(sacc[ni], af, bf);
            }
        }

        // ---- online softmax ----
        float mx0 = -3.4e38f, mx1 = -3.4e38f;
#pragma unroll
        for (int ni = 0; ni < 8; ni++) {
            mx0 = fmaxf(mx0, fmaxf(sacc[ni][0], sacc[ni][1]));
            mx1 = fmaxf(mx1, fmaxf(sacc[ni][2], sacc[ni][3]));
        }
        mx0 = fmaxf(mx0, __shfl_xor_sync(0xffffffffu, mx0, 1));
        mx0 = fmaxf(mx0, __shfl_xor_sync(0xffffffffu, mx0, 2));
        mx1 = fmaxf(mx1, __shfl_xor_sync(0xffffffffu, mx1, 1));
        mx1 = fmaxf(mx1, __shfl_xor_sync(0xffffffffu, mx1, 2));
        const float mn0 = fmaxf(m0v, mx0);
        const float mn1 = fmaxf(m1v, mx1);
        const float a0 = __expf(m0v - mn0);
        const float a1 = __expf(m1v - mn1);
        m0v = mn0; m1v = mn1;

        float s0 = 0.f, s1 = 0.f;
#pragma unroll
        for (int ni = 0; ni < 8; ni++) {
            float p0 = __expf(sacc[ni][0] - mn0);
            float p1 = __expf(sacc[ni][1] - mn0);
            float p2 = __expf(sacc[ni][2] - mn1);
            float p3 = __expf(sacc[ni][3] - mn1);
            s0 += p0 + p1; s1 += p2 + p3;
            const int col = ni * 8 + tig * 2;
            PS(wm + gid, col) = f2t(p0);
            PS(wm + gid, col + 1) = f2t(p1);
            PS(wm + gid + 8, col) = f2t(p2);
            PS(wm + gid + 8, col + 1) = f2t(p3);
        }
        s0 += __shfl_xor_sync(0xffffffffu, s0, 1);
        s0 += __shfl_xor_sync(0xffffffffu, s0, 2);
        s1 += __shfl_xor_sync(0xffffffffu, s1, 1);
        s1 += __shfl_xor_sync(0xffffffffu, s1, 2);
        l0 = l0 * a0 + s0;
        l1 = l1 * a1 + s1;

        // rescale O
#pragma unroll
        for (int ni = 0; ni < 8; ni++) {
            o[ni][0] *= a0; o[ni][1] *= a0;
            o[ni][2] *= a1; o[ni][3] *= a1;
        }
        __syncwarp();

        // ---- O += P @ V ----
#pragma unroll
        for (int ks = 0; ks < 64; ks += 8) {
            uint32_t af[4];
            af[0] = PS(wm + gid, ks + tig);
            af[1] = PS(wm + gid + 8, ks + tig);
            af[2] = PS(wm + gid, ks + tig + 4);
            af[3] = PS(wm + gid + 8, ks + tig + 4);
#pragma unroll
            for (int ni = 0; ni < 8; ni++) {
                uint32_t bf[2];
                bf[0] = VS(ks + tig, ni * 8 + gid);
                bf[1] = VS(ks + tig + 4, ni * 8 + gid);
                mma_tf32(o[ni], af, bf);
            }
        }
        __syncthreads();
    }

    // ---- write O (normalized) ----
    const float inv0 = 1.f / l0;
    const float inv1 = 1.f / l1;
    const long r0 = (long)(b * S_ + q0 + wm + gid) * D_ + h * DH_;
    const long r1 = r0 + 8 * D_;
#pragma unroll
    for (int ni = 0; ni < 8; ni++) {
        const int col = ni * 8 + tig * 2;
        *(float2*)(g_attn + r0 + col) = make_float2(o[ni][0] * inv0, o[ni][1] * inv0);
        *(float2*)(g_attn + r1 + col) = make_float2(o[ni][2] * inv1, o[ni][3] * inv1);
    }
#undef QS
#undef PS
#undef KS
#undef VS
}

// ---------------- elementwise / LN ---------------------------------------------
__global__ void k_zero()
{
    long i = (long)blockIdx.x * 256 + threadIdx.x;
    if (i < ND_) g_moe[i] = 0.f;
    if (i < E_) { g_cnt[i] = 0; g_cur[i] = 0; g_loadcnt[i] = 0; }
}

__global__ void k_addln(const float* __restrict__ a, const float* __restrict__ b,
                        const float* __restrict__ g, const float* __restrict__ be,
                        float* __restrict__ out)
{
    __shared__ float buf[D_];
    __shared__ float red[256];
    const int t = blockIdx.x;
    const int tid = threadIdx.x;
    const float* pa = a + (long)t * D_;
    const float* pb = b + (long)t * D_;
    float s = 0.f;
    for (int i = tid; i < D_; i += 256) { float v = pa[i] + pb[i]; buf[i] = v; s += v; }
    red[tid] = s; __syncthreads();
    for (int o = 128; o > 0; o >>= 1) { if (tid < o) red[tid] += red[tid + o]; __syncthreads(); }
    float mean = red[0] * (1.f / D_);
    __syncthreads();
    float vs = 0.f;
    for (int i = tid; i < D_; i += 256) { float d = buf[i] - mean; vs += d * d; }
    red[tid] = vs; __syncthreads();
    for (int o = 128; o > 0; o >>= 1) { if (tid < o) red[tid] += red[tid + o]; __syncthreads(); }
    float rstd = rsqrtf(red[0] * (1.f / D_) + 1e-5f);
    float* po = out + (long)t * D_;
    for (int i = tid; i < D_; i += 256)
        po[i] = (buf[i] - mean) * rstd * g[i] + be[i];
}

// ---------------- router / dispatch / aux --------------------------------------
__device__ __forceinline__ void router_core(const float* __restrict__ x,
                                            const float* __restrict__ rw,
                                            const float* __restrict__ rb,
                                            int lane, float* probs_out,
                                            int* i1_out, int* i2_out)
{
    float le[E_];
#pragma unroll
    for (int e = 0; e < E_; e++) le[e] = 0.f;
    for (int d0 = lane * 4; d0 < D_; d0 += 128) {
        float4 xv = *(const float4*)(x + d0);
        float xa[4] = {xv.x, xv.y, xv.z, xv.w};
#pragma unroll
        for (int r = 0; r < 4; r++) {
            const float* w = rw + (long)(d0 + r) * E_;
            float4 w0 = *(const float4*)(w);
            float4 w1 = *(const float4*)(w + 4);
            le[0] = fmaf(xa[r], w0.x, le[0]); le[1] = fmaf(xa[r], w0.y, le[1]);
            le[2] = fmaf(xa[r], w0.z, le[2]); le[3] = fmaf(xa[r], w0.w, le[3]);
            le[4] = fmaf(xa[r], w1.x, le[4]); le[5] = fmaf(xa[r], w1.y, le[5]);
            le[6] = fmaf(xa[r], w1.z, le[6]); le[7] = fmaf(xa[r], w1.w, le[7]);
        }
    }
#pragma unroll
    for (int e = 0; e < E_; e++)
        for (int o = 16; o > 0; o >>= 1) le[e] += __shfl_xor_sync(0xffffffffu, le[e], o);
    float mx = -3.4e38f;
#pragma unroll
    for (int e = 0; e < E_; e++) { le[e] += rb[e]; mx = fmaxf(mx, le[e]); }
    float sum = 0.f;
#pragma unroll
    for (int e = 0; e < E_; e++) { le[e] = expf(le[e] - mx); sum += le[e]; }
    float inv = 1.f / sum;
#pragma unroll
    for (int e = 0; e < E_; e++) { le[e] *= inv; probs_out[e] = le[e]; }
    int i1 = 0;
    for (int e = 1; e < E_; e++) if (le[e] > le[i1]) i1 = e;
    int i2 = (i1 == 0) ? 1 : 0;
    for (int e = 0; e < E_; e++) if (e != i1 && le[e] > le[i2]) i2 = e;
    *i1_out = i1; *i2_out = i2;
}

__global__ void k_router(const float* __restrict__ rw, const float* __restrict__ rb)
{
    const int warp = threadIdx.x >> 5, lane = threadIdx.x & 31;
    const int t = blockIdx.x * 8 + warp;
    if (t >= N_) return;
    float probs[E_]; int i1, i2;
    router_core(g_x2 + (long)t * D_, rw, rb, lane, probs, &i1, &i2);
    if (lane == 0) {
        float gs = probs[i1] + probs[i2];
        g_topi[t * 2] = i1; g_topi[t * 2 + 1] = i2;
        g_gate[t * 2] = probs[i1] / gs; g_gate[t * 2 + 1] = probs[i2] / gs;
        atomicAdd(&g_cnt[i1], 1); atomicAdd(&g_cnt[i2], 1);
    }
}

__global__ void k_scan()
{
    if (threadIdx.x == 0) {
        int s = 0;
        for (int e = 0; e < E_; e++) { g_off[e] = s; s += g_cnt[e]; }
    }
}

__global__ void k_fill()
{
    int t = blockIdx.x * 256 + threadIdx.x;
    if (t >= N_) return;
#pragma unroll
    for (int k = 0; k < K_; k++) {
        int e = g_topi[t * K_ + k];
        int p = atomicAdd(&g_cur[e], 1);
        int d = g_off[e] + p;
        g_dtok[d] = t;
        g_dgate[d] = g_gate[t * K_ + k];
    }
}

__global__ void k_aux_router(const float* __restrict__ X,
                             const float* __restrict__ rw, const float* __restrict__ rb)
{
    const int warp = threadIdx.x >> 5, lane = threadIdx.x & 31;
    const int t = blockIdx.x * 8 + warp;
    if (t >= N_) return;
    float probs[E_]; int i1, i2;
    router_core(X + (long)t * D_, rw, rb, lane, probs, &i1, &i2);
    if (lane == 0) {
#pragma unroll
        for (int e = 0; e < E_; e++) g_probs[t * E_ + e] = probs[e];
        atomicAdd(&g_loadcnt[i1], 1); atomicAdd(&g_loadcnt[i2], 1);
    }
}

__global__ void k_aux_reduce(float* __restrict__ out, int write)
{
    __shared__ float red[256];
    const int tid = threadIdx.x;
    float imp[E_];
#pragma unroll
    for (int e = 0; e < E_; e++) imp[e] = 0.f;
    for (int t = tid; t < N_; t += 256)
#pragma unroll
        for (int e = 0; e < E_; e++) imp[e] += g_probs[t * E_ + e];
    float aux = 0.f;
    for (int e = 0; e < E_; e++) {
        red[tid] = imp[e]; __syncthreads();
        for (int o = 128; o > 0; o >>= 1) { if (tid < o) red[tid] += red[tid + o]; __syncthreads(); }
        if (tid == 0)
            aux += (red[0] / (float)N_) * ((float)g_loadcnt[e] / (float)(N_ * K_));
        __syncthreads();
    }
    if (tid == 0 && write) out[ND_] = aux * (float)E_;
}

// ---------------- launch ------------------------------------------------------
extern "C" void kernel_launch(void* const* d_in, const int* in_sizes, int n_in,
                              void* d_out, int out_size)
{
    (void)in_sizes; (void)n_in;
    const float* x     = (const float*)d_in[0];
    const float* enc   = (const float*)d_in[1];
    const float* sa_wq = (const float*)d_in[2];
    const float* sa_bq = (const float*)d_in[3];
    const float* sa_wk = (const float*)d_in[4];
    const float* sa_bk = (const float*)d_in[5];
    const float* sa_wv = (const float*)d_in[6];
    const float* sa_bv = (const float*)d_in[7];
    const float* sa_wo = (const float*)d_in[8];
    const float* sa_bo = (const float*)d_in[9];
    const float* ca_wq = (const float*)d_in[10];
    const float* ca_bq = (const float*)d_in[11];
    const float* ca_wk = (const float*)d_in[12];
    const float* ca_bk = (const float*)d_in[13];
    const float* ca_wv = (const float*)d_in[14];
    const float* ca_bv = (const float*)d_in[15];
    const float* ca_wo = (const float*)d_in[16];
    const float* ca_bo = (const float*)d_in[17];
    const float* n1_g  = (const float*)d_in[18];
    const float* n1_b  = (const float*)d_in[19];
    const float* n2_g  = (const float*)d_in[20];
    const float* n2_b  = (const float*)d_in[21];
    const float* n3_g  = (const float*)d_in[22];
    const float* n3_b  = (const float*)d_in[23];
    const float* r_w   = (const float*)d_in[24];
    const float* r_b   = (const float*)d_in[25];
    const float* e_w1  = (const float*)d_in[26];
    const float* e_b1  = (const float*)d_in[27];
    const float* e_w2  = (const float*)d_in[28];
    const float* e_b2  = (const float*)d_in[29];
    float* out = (float*)d_out;

    float *pq, *pk, *pv, *pattn, *pt, *px1, *px2, *pmoe;
    cudaGetSymbolAddress((void**)&pq, g_q);
    cudaGetSymbolAddress((void**)&pk, g_k);
    cudaGetSymbolAddress((void**)&pv, g_v);
    cudaGetSymbolAddress((void**)&pattn, g_attn);
    cudaGetSymbolAddress((void**)&pt, g_t);
    cudaGetSymbolAddress((void**)&px1, g_x1);
    cudaGetSymbolAddress((void**)&px2, g_x2);
    cudaGetSymbolAddress((void**)&pmoe, g_moe);

    static int s_attr_done = 0;
    if (!s_attr_done) {
        cudaFuncSetAttribute(k_flash, cudaFuncAttributeMaxDynamicSharedMemorySize,
                             FL_SMEM_WORDS * 4);
        s_attr_done = 1;
    }

    dim3 blk(256);
    dim3 gProj(D_ / 64, N_ / 128);             // (16, 32) = 512 blocks
    dim3 gFlash(S_ / 128, BH_);                // (16, 32)

    k_zero<<<(N_ * D_) / 256, blk>>>();

    // ---- self attention ----
    k_gemm64<<<gProj, blk>>>(x, sa_wq, sa_bq, pq, N_, D_, D_, D_, D_, D_);
    k_gemm64<<<gProj, blk>>>(x, sa_wk, sa_bk, pk, N_, D_, D_, D_, D_, D_);
    k_gemm64<<<gProj, blk>>>(x, sa_wv, sa_bv, pv, N_, D_, D_, D_, D_, D_);
    k_flash<<<gFlash, blk, FL_SMEM_WORDS * 4>>>();
    k_gemm64<<<gProj, blk>>>(pattn, sa_wo, sa_bo, pt, N_, D_, D_, D_, D_, D_);
    k_addln<<<N_, blk>>>(x, pt, n1_g, n1_b, px1);

    // ---- cross attention ----
    k_gemm64<<<gProj, blk>>>(px1, ca_wq, ca_bq, pq, N_, D_, D_, D_, D_, D_);
    k_gemm64<<<gProj, blk>>>(enc, ca_wk, ca_bk, pk, N_, D_, D_, D_, D_, D_);
    k_gemm64<<<gProj, blk>>>(enc, ca_wv, ca_bv, pv, N_, D_, D_, D_, D_, D_);
    k_flash<<<gFlash, blk, FL_SMEM_WORDS * 4>>>();
    k_gemm64<<<gProj, blk>>>(pattn, ca_wo, ca_bo, pt, N_, D_, D_, D_, D_, D_);
    k_addln<<<N_, blk>>>(px1, pt, n2_g, n2_b, px2);

    // ---- MoE (sparse top-2 dispatch) ----
    k_router<<<N_ / 8, blk>>>(r_w, r_b);
    k_scan<<<1, 32>>>();
    k_fill<<<N_ / 256, blk>>>();
    k_ff1<<<dim3(F_ / 128, N_ / 128, E_), blk>>>(e_w1, e_b1);
    k_ff2<<<dim3(D_ / 128, N_ / 128, E_), blk>>>(e_w2, e_b2);
    k_addln<<<N_, blk>>>(px2, pmoe, n3_g, n3_b, out);

    // ---- aux loss on final output ----
    k_aux_router<<<N_ / 8, blk>>>(out, r_w, r_b);
    k_aux_reduce<<<1, blk>>>(out, ((long)out_size > ND_) ? 1 : 0);
}

// round 4
// speedup vs baseline: 3.0865x; 1.2773x over previous
#include <cuda_runtime.h>
#include <math.h>
#include <stdint.h>

#define D_  1024
#define H_  16
#define DH_ 64
#define F_  4096
#define E_  8
#define K_  2
#define B_  2
#define S_  2048
#define N_  (B_ * S_)          // 4096 tokens
#define BH_ (B_ * H_)          // 32
#define ND_ ((long)N_ * D_)    // 4194304

// ---------------- scratch (device globals; no allocation allowed) -------------
__device__ float g_q[N_ * D_];
__device__ float g_k[N_ * D_];
__device__ float g_v[N_ * D_];
__device__ float g_attn[N_ * D_];
__device__ float g_t[N_ * D_];
__device__ float g_x1[N_ * D_];
__device__ float g_x2[N_ * D_];
__device__ float g_moe[N_ * D_];
__device__ float g_s[(long)N_ * K_ * F_];   // MoE hidden (128MB)

__device__ int   g_topi[N_ * K_];
__device__ float g_gate[N_ * K_];
__device__ int   g_cnt[E_];
__device__ int   g_off[E_];
__device__ int   g_cur[E_];
__device__ int   g_dtok[N_ * K_];
__device__ float g_dgate[N_ * K_];
__device__ float g_probs[N_ * E_];
__device__ int   g_loadcnt[E_];

// ---------------- mma / cp.async helpers ---------------------------------------
__device__ __forceinline__ void mma_tf32(float* c, const uint32_t* a, const uint32_t* b)
{
    asm volatile(
        "mma.sync.aligned.m16n8k8.row.col.f32.tf32.tf32.f32 "
        "{%0,%1,%2,%3}, {%4,%5,%6,%7}, {%8,%9}, {%0,%1,%2,%3};\n"
        : "+f"(c[0]), "+f"(c[1]), "+f"(c[2]), "+f"(c[3])
        : "r"(a[0]), "r"(a[1]), "r"(a[2]), "r"(a[3]), "r"(b[0]), "r"(b[1]));
}

__device__ __forceinline__ void cp16(uint32_t dst, const void* src, int srcbytes)
{
    asm volatile("cp.async.cg.shared.global [%0], [%1], 16, %2;\n"
                 :: "r"(dst), "l"(src), "r"(srcbytes));
}
#define CP_COMMIT asm volatile("cp.async.commit_group;\n")
#define CP_WAIT1  asm volatile("cp.async.wait_group 1;\n")
#define CP_WAIT0  asm volatile("cp.async.wait_group 0;\n")

// ---------------- double-buffered tf32 GEMM core (128x128 tile) ---------------
// 256 threads, 8 warps in 2(M)x4(N) grid, warp tile 64x32 (MI=4, NI=4), TBK=16.
// A smem row-major stride 20 (fragment LDS: gid*20+tig -> 32 distinct banks).
// B smem row-major stride 136 (tig*136+gid -> 32 distinct banks).
#define TBK 16
#define AST 20
#define BST 136

template<bool GATHER, bool RELU, bool SCATTER>
__device__ __forceinline__ void gemm128_db(
    const float* __restrict__ A, int lda,
    const float* __restrict__ B, int ldb,
    float* __restrict__ C, int ldc,
    int M, int K, int n0,
    const float* __restrict__ bias,
    const int* __restrict__ gidx,
    const int* __restrict__ sidx,
    const float* __restrict__ rscale)
{
    __shared__ float As[2][128 * AST];
    __shared__ float Bs[2][TBK * BST];

    const int tid = threadIdx.x;
    const int m0 = blockIdx.y * 128;
    if (m0 >= M) return;

    const int w = tid >> 5;
    const int lane = tid & 31;
    const int gid = lane >> 2;
    const int tig = lane & 3;
    const int wm = (w & 1) * 64;
    const int wn = (w >> 1) * 32;

    float acc[4][4][4];
#pragma unroll
    for (int mi = 0; mi < 4; mi++)
#pragma unroll
        for (int ni = 0; ni < 4; ni++)
#pragma unroll
            for (int r = 0; r < 4; r++) acc[mi][ni][r] = 0.f;

    // A loader: row = tid>>1 (128 rows), 8 floats starting at (tid&1)*8
    const int ar = tid >> 1;
    const int ac = (tid & 1) * 8;
    const bool avalid = (m0 + ar) < M;
    long grow = 0;
    if (avalid) grow = GATHER ? (long)gidx[m0 + ar] : (long)(m0 + ar);
    const float* Ap = A + grow * (long)lda + ac;   // clamped to row 0 if invalid
    const int ab = avalid ? 16 : 0;

    // B loader: row = tid>>4 (16 rows), 8 floats at (tid&15)*8
    const int br = tid >> 4;
    const int bc = (tid & 15) * 8;
    const float* Bp = B + (long)br * ldb + n0 + bc;

    uint32_t adst[2], bdst[2];
    adst[0] = (uint32_t)__cvta_generic_to_shared(&As[0][ar * AST + ac]);
    adst[1] = (uint32_t)__cvta_generic_to_shared(&As[1][ar * AST + ac]);
    bdst[0] = (uint32_t)__cvta_generic_to_shared(&Bs[0][br * BST + bc]);
    bdst[1] = (uint32_t)__cvta_generic_to_shared(&Bs[1][br * BST + bc]);

    const int KT = K / TBK;

    // prologue: stage 0
    cp16(adst[0], Ap, ab);
    cp16(adst[0] + 16, Ap + 4, ab);
    cp16(bdst[0], Bp, 16);
    cp16(bdst[0] + 16, Bp + 4, 16);
    CP_COMMIT;

    for (int kt = 0; kt < KT; kt++) {
        const int cur = kt & 1;
        if (kt + 1 < KT) {
            const float* ap = Ap + (kt + 1) * TBK;
            cp16(adst[cur ^ 1], ap, ab);
            cp16(adst[cur ^ 1] + 16, ap + 4, ab);
            const float* bp = Bp + (long)(kt + 1) * TBK * ldb;
            cp16(bdst[cur ^ 1], bp, 16);
            cp16(bdst[cur ^ 1] + 16, bp + 4, 16);
            CP_COMMIT;
            CP_WAIT1;
        } else {
            CP_WAIT0;
        }
        __syncthreads();

        const float* as = As[cur];
        const float* bs = Bs[cur];
#pragma unroll
        for (int ks = 0; ks < TBK; ks += 8) {
            uint32_t af[4][4], bf[4][2];
#pragma unroll
            for (int mi = 0; mi < 4; mi++) {
                const int mrow = wm + mi * 16 + gid;
                af[mi][0] = __float_as_uint(as[mrow * AST + ks + tig]);
                af[mi][1] = __float_as_uint(as[(mrow + 8) * AST + ks + tig]);
                af[mi][2] = __float_as_uint(as[mrow * AST + ks + tig + 4]);
                af[mi][3] = __float_as_uint(as[(mrow + 8) * AST + ks + tig + 4]);
            }
#pragma unroll
            for (int ni = 0; ni < 4; ni++) {
                const int ncol = wn + ni * 8 + gid;
                bf[ni][0] = __float_as_uint(bs[(ks + tig) * BST + ncol]);
                bf[ni][1] = __float_as_uint(bs[(ks + tig + 4) * BST + ncol]);
            }
#pragma unroll
            for (int mi = 0; mi < 4; mi++)
#pragma unroll
                for (int ni = 0; ni < 4; ni++)
                    mma_tf32(acc[mi][ni], af[mi], bf[ni]);
        }
        __syncthreads();
    }

    // epilogue (c0:(r,c) c1:(r,c+1) c2:(r+8,c) c3:(r+8,c+1))
#pragma unroll
    for (int mi = 0; mi < 4; mi++) {
#pragma unroll
        for (int half = 0; half < 2; half++) {
            const int row = m0 + wm + mi * 16 + gid + half * 8;
            if (row >= M) continue;
            float sc = 1.f;
            long crow = row;
            if constexpr (SCATTER) { sc = rscale[row]; crow = sidx[row]; }
            float* cp = C + crow * (long)ldc;
#pragma unroll
            for (int ni = 0; ni < 4; ni++) {
                const int col = n0 + wn + ni * 8 + tig * 2;
                float v0 = acc[mi][ni][half * 2 + 0];
                float v1 = acc[mi][ni][half * 2 + 1];
                if (bias) { v0 += bias[col]; v1 += bias[col + 1]; }
                if constexpr (RELU) { v0 = fmaxf(v0, 0.f); v1 = fmaxf(v1, 0.f); }
                if constexpr (SCATTER) {
                    atomicAdd(cp + col, v0 * sc);
                    atomicAdd(cp + col + 1, v1 * sc);
                } else {
                    *(float2*)(cp + col) = make_float2(v0, v1);
                }
            }
        }
    }
}

// ---------------- GEMM wrappers -------------------------------------------------
// batched triple projection (z selects which GEMM)
__global__ void __launch_bounds__(256) k_proj3(
    const float* a0, const float* a1, const float* a2,
    const float* w0, const float* w1, const float* w2,
    const float* bi0, const float* bi1, const float* bi2,
    float* c0, float* c1, float* c2)
{
    const float *A, *W, *bi;
    float* C;
    if (blockIdx.z == 0)      { A = a0; W = w0; bi = bi0; C = c0; }
    else if (blockIdx.z == 1) { A = a1; W = w1; bi = bi1; C = c1; }
    else                      { A = a2; W = w2; bi = bi2; C = c2; }
    gemm128_db<false, false, false>(A, D_, W, D_, C, D_, N_, D_, blockIdx.x * 128,
                                    bi, nullptr, nullptr, nullptr);
}

__global__ void __launch_bounds__(256) k_proj1(
    const float* __restrict__ A, const float* __restrict__ W,
    const float* __restrict__ bi, float* __restrict__ C)
{
    gemm128_db<false, false, false>(A, D_, W, D_, C, D_, N_, D_, blockIdx.x * 128,
                                    bi, nullptr, nullptr, nullptr);
}

// MoE FF1: h = relu(gather(x2) @ W1[e] + b1[e]) into g_s
__global__ void __launch_bounds__(256) k_ff1(
    const float* __restrict__ W1, const float* __restrict__ B1)
{
    const int e = blockIdx.z;
    const int cnt = g_cnt[e];
    if ((int)(blockIdx.y * 128) >= cnt) return;
    const int off = g_off[e];
    gemm128_db<true, true, false>(
        g_x2, D_, W1 + (long)e * D_ * F_, F_,
        g_s + (long)off * F_, F_,
        cnt, D_, blockIdx.x * 128, B1 + (long)e * F_,
        g_dtok + off, nullptr, nullptr);
}

// MoE FF2: moe_out[tok] += gate * (h @ W2[e] + b2[e])   (atomic scatter)
__global__ void __launch_bounds__(256) k_ff2(
    const float* __restrict__ W2, const float* __restrict__ B2)
{
    const int e = blockIdx.z;
    const int cnt = g_cnt[e];
    if ((int)(blockIdx.y * 128) >= cnt) return;
    const int off = g_off[e];
    gemm128_db<false, false, true>(
        g_s + (long)off * F_, F_, W2 + (long)e * F_ * D_, D_,
        g_moe, D_, cnt, F_, blockIdx.x * 128, B2 + (long)e * D_,
        nullptr, g_dtok + off, g_dgate + off);
}

// ---------------- flash attention ---------------------------------------------
// One block = one (batch,head) and one 128-row query tile. 256 threads, 8 warps,
// each warp owns 16 query rows. K/V streamed in 64-row tiles (cp.async), online
// softmax, raw fp32 bits as tf32 operands; S scaled by 1/8 after MMA (exact).
#define QS_OFF 0
#define PS_OFF 8704
#define KS_OFF 17408
#define VS_OFF 21760
#define FL_SMEM_WORDS 26368   // *4 = 105472 bytes

__global__ void __launch_bounds__(256) k_flash()
{
    extern __shared__ float sm[];
#define QS(r, c) sm[QS_OFF + (r) * 68 + (c)]
#define PS(r, c) sm[PS_OFF + (r) * 68 + (c)]
#define KS(r, c) sm[KS_OFF + (r) * 68 + (c)]
#define VS(r, c) sm[VS_OFF + (r) * 72 + (c)]

    const int tid = threadIdx.x;
    const int w = tid >> 5;
    const int lane = tid & 31;
    const int gid = lane >> 2;
    const int tig = lane & 3;
    const int wm = w * 16;

    const int qb = blockIdx.x;
    const int z = blockIdx.y;
    const int b = z >> 4, h = z & 15;
    const int q0 = qb * 128;

    // ---- Q tile (128 x 64) via cp.async ----
    {
        const int r = tid >> 1;
        const int c0 = (tid & 1) * 32;
        const float* qp = g_q + ((long)(b * S_ + q0 + r)) * D_ + h * DH_ + c0;
        uint32_t qd = (uint32_t)__cvta_generic_to_shared(&QS(r, c0));
#pragma unroll
        for (int i = 0; i < 8; i++) cp16(qd + i * 16, qp + i * 4, 16);
    }

    const int ls = tid >> 2;
    const int ld0 = (tid & 3) * 16;
    const long kvb = ((long)(b * S_ + ls)) * D_ + h * DH_ + ld0;
    uint32_t kd = (uint32_t)__cvta_generic_to_shared(&KS(ls, ld0));
    uint32_t vd = (uint32_t)__cvta_generic_to_shared(&VS(ls, ld0));

    // first K/V tile
    {
        const float* kp = g_k + kvb;
        const float* vp = g_v + kvb;
#pragma unroll
        for (int i = 0; i < 4; i++) {
            cp16(kd + i * 16, kp + i * 4, 16);
            cp16(vd + i * 16, vp + i * 4, 16);
        }
    }
    CP_COMMIT;

    float m0v = -3.4e38f, m1v = -3.4e38f;
    float l0 = 0.f, l1 = 0.f;
    float o[8][4];
#pragma unroll
    for (int ni = 0; ni < 8; ni++)
#pragma unroll
        for (int r = 0; r < 4; r++) o[ni][r] = 0.f;

    for (int j = 0; j < S_ / 64; j++) {
        CP_WAIT0;
        __syncthreads();

        // ---- S = Q @ K^T (warp: 16 rows x 64 keys), then * 0.125 ----
        float sacc[8][4];
#pragma unroll
        for (int ni = 0; ni < 8; ni++)
#pragma unroll
            for (int r = 0; r < 4; r++) sacc[ni][r] = 0.f;
#pragma unroll
        for (int ks = 0; ks < 64; ks += 8) {
            uint32_t af[4];
            af[0] = __float_as_uint(QS(wm + gid, ks + tig));
            af[1] = __float_as_uint(QS(wm + gid + 8, ks + tig));
            af[2] = __float_as_uint(QS(wm + gid, ks + tig + 4));
            af[3] = __float_as_uint(QS(wm + gid + 8, ks + tig + 4));
#pragma unroll
            for (int ni = 0; ni < 8; ni++) {
                uint32_t bf[2];
                bf[0] = __float_as_uint(KS(ni * 8 + gid, ks + tig));
                bf[1] = __float_as_uint(KS(ni * 8 + gid, ks + tig + 4));
                mma_tf32(sacc[ni], af, bf);
            }
        }
#pragma unroll
        for (int ni = 0; ni < 8; ni++)
#pragma unroll
            for (int r = 0; r < 4; r++) sacc[ni][r] *= 0.125f;

        // ---- online softmax ----
        float mx0 = -3.4e38f, mx1 = -3.4e38f;
#pragma unroll
        for (int ni = 0; ni < 8; ni++) {
            mx0 = fmaxf(mx0, fmaxf(sacc[ni][0], sacc[ni][1]));
            mx1 = fmaxf(mx1, fmaxf(sacc[ni][2], sacc[ni][3]));
        }
        mx0 = fmaxf(mx0, __shfl_xor_sync(0xffffffffu, mx0, 1));
        mx0 = fmaxf(mx0, __shfl_xor_sync(0xffffffffu, mx0, 2));
        mx1 = fmaxf(mx1, __shfl_xor_sync(0xffffffffu, mx1, 1));
        mx1 = fmaxf(mx1, __shfl_xor_sync(0xffffffffu, mx1, 2));
        const float mn0 = fmaxf(m0v, mx0);
        const float mn1 = fmaxf(m1v, mx1);
        const float a0 = __expf(m0v - mn0);
        const float a1 = __expf(m1v - mn1);
        m0v = mn0; m1v = mn1;

        float s0 = 0.f, s1 = 0.f;
#pragma unroll
        for (int ni = 0; ni < 8; ni++) {
            float p0 = __expf(sacc[ni][0] - mn0);
            float p1 = __expf(sacc[ni][1] - mn0);
            float p2 = __expf(sacc[ni][2] - mn1);
            float p3 = __expf(sacc[ni][3] - mn1);
            s0 += p0 + p1; s1 += p2 + p3;
            const int col = ni * 8 + tig * 2;
            PS(wm + gid, col) = p0;
            PS(wm + gid, col + 1) = p1;
            PS(wm + gid + 8, col) = p2;
            PS(wm + gid + 8, col + 1) = p3;
        }
        s0 += __shfl_xor_sync(0xffffffffu, s0, 1);
        s0 += __shfl_xor_sync(0xffffffffu, s0, 2);
        s1 += __shfl_xor_sync(0xffffffffu, s1, 1);
        s1 += __shfl_xor_sync(0xffffffffu, s1, 2);
        l0 = l0 * a0 + s0;
        l1 = l1 * a1 + s1;

#pragma unroll
        for (int ni = 0; ni < 8; ni++) {
            o[ni][0] *= a0; o[ni][1] *= a0;
            o[ni][2] *= a1; o[ni][3] *= a1;
        }
        __syncwarp();

        // ---- O += P @ V ----
#pragma unroll
        for (int ks = 0; ks < 64; ks += 8) {
            uint32_t af[4];
            af[0] = __float_as_uint(PS(wm + gid, ks + tig));
            af[1] = __float_as_uint(PS(wm + gid + 8, ks + tig));
            af[2] = __float_as_uint(PS(wm + gid, ks + tig + 4));
            af[3] = __float_as_uint(PS(wm + gid + 8, ks + tig + 4));
#pragma unroll
            for (int ni = 0; ni < 8; ni++) {
                uint32_t bf[2];
                bf[0] = __float_as_uint(VS(ks + tig, ni * 8 + gid));
                bf[1] = __float_as_uint(VS(ks + tig + 4, ni * 8 + gid));
                mma_tf32(o[ni], af, bf);
            }
        }
        __syncthreads();

        if (j + 1 < S_ / 64) {
            const float* kp = g_k + kvb + (long)(j + 1) * 64 * D_;
            const float* vp = g_v + kvb + (long)(j + 1) * 64 * D_;
#pragma unroll
            for (int i = 0; i < 4; i++) {
                cp16(kd + i * 16, kp + i * 4, 16);
                cp16(vd + i * 16, vp + i * 4, 16);
            }
            CP_COMMIT;
        }
    }

    // ---- write O (normalized) ----
    const float inv0 = 1.f / l0;
    const float inv1 = 1.f / l1;
    const long r0 = (long)(b * S_ + q0 + wm + gid) * D_ + h * DH_;
    const long r1 = r0 + 8 * D_;
#pragma unroll
    for (int ni = 0; ni < 8; ni++) {
        const int col = ni * 8 + tig * 2;
        *(float2*)(g_attn + r0 + col) = make_float2(o[ni][0] * inv0, o[ni][1] * inv0);
        *(float2*)(g_attn + r1 + col) = make_float2(o[ni][2] * inv1, o[ni][3] * inv1);
    }
#undef QS
#undef PS
#undef KS
#undef VS
}

// ---------------- elementwise / LN ---------------------------------------------
__global__ void k_zero()
{
    long i = (long)blockIdx.x * 256 + threadIdx.x;
    if (i < ND_) g_moe[i] = 0.f;
    if (i < E_) { g_cnt[i] = 0; g_cur[i] = 0; g_loadcnt[i] = 0; }
}

__global__ void k_addln(const float* __restrict__ a, const float* __restrict__ b,
                        const float* __restrict__ g, const float* __restrict__ be,
                        float* __restrict__ out)
{
    __shared__ float buf[D_];
    __shared__ float red[256];
    const int t = blockIdx.x;
    const int tid = threadIdx.x;
    const float* pa = a + (long)t * D_;
    const float* pb = b + (long)t * D_;
    float s = 0.f;
    for (int i = tid; i < D_; i += 256) { float v = pa[i] + pb[i]; buf[i] = v; s += v; }
    red[tid] = s; __syncthreads();
    for (int o = 128; o > 0; o >>= 1) { if (tid < o) red[tid] += red[tid + o]; __syncthreads(); }
    float mean = red[0] * (1.f / D_);
    __syncthreads();
    float vs = 0.f;
    for (int i = tid; i < D_; i += 256) { float d = buf[i] - mean; vs += d * d; }
    red[tid] = vs; __syncthreads();
    for (int o = 128; o > 0; o >>= 1) { if (tid < o) red[tid] += red[tid + o]; __syncthreads(); }
    float rstd = rsqrtf(red[0] * (1.f / D_) + 1e-5f);
    float* po = out + (long)t * D_;
    for (int i = tid; i < D_; i += 256)
        po[i] = (buf[i] - mean) * rstd * g[i] + be[i];
}

// ---------------- router / dispatch / aux --------------------------------------
__device__ __forceinline__ void router_core(const float* __restrict__ x,
                                            const float* __restrict__ rw,
                                            const float* __restrict__ rb,
                                            int lane, float* probs_out,
                                            int* i1_out, int* i2_out)
{
    float le[E_];
#pragma unroll
    for (int e = 0; e < E_; e++) le[e] = 0.f;
    for (int d0 = lane * 4; d0 < D_; d0 += 128) {
        float4 xv = *(const float4*)(x + d0);
        float xa[4] = {xv.x, xv.y, xv.z, xv.w};
#pragma unroll
        for (int r = 0; r < 4; r++) {
            const float* w = rw + (long)(d0 + r) * E_;
            float4 w0 = *(const float4*)(w);
            float4 w1 = *(const float4*)(w + 4);
            le[0] = fmaf(xa[r], w0.x, le[0]); le[1] = fmaf(xa[r], w0.y, le[1]);
            le[2] = fmaf(xa[r], w0.z, le[2]); le[3] = fmaf(xa[r], w0.w, le[3]);
            le[4] = fmaf(xa[r], w1.x, le[4]); le[5] = fmaf(xa[r], w1.y, le[5]);
            le[6] = fmaf(xa[r], w1.z, le[6]); le[7] = fmaf(xa[r], w1.w, le[7]);
        }
    }
#pragma unroll
    for (int e = 0; e < E_; e++)
        for (int o = 16; o > 0; o >>= 1) le[e] += __shfl_xor_sync(0xffffffffu, le[e], o);
    float mx = -3.4e38f;
#pragma unroll
    for (int e = 0; e < E_; e++) { le[e] += rb[e]; mx = fmaxf(mx, le[e]); }
    float sum = 0.f;
#pragma unroll
    for (int e = 0; e < E_; e++) { le[e] = expf(le[e] - mx); sum += le[e]; }
    float inv = 1.f / sum;
#pragma unroll
    for (int e = 0; e < E_; e++) { le[e] *= inv; probs_out[e] = le[e]; }
    int i1 = 0;
    for (int e = 1; e < E_; e++) if (le[e] > le[i1]) i1 = e;
    int i2 = (i1 == 0) ? 1 : 0;
    for (int e = 0; e < E_; e++) if (e != i1 && le[e] > le[i2]) i2 = e;
    *i1_out = i1; *i2_out = i2;
}

__global__ void k_router(const float* __restrict__ rw, const float* __restrict__ rb)
{
    const int warp = threadIdx.x >> 5, lane = threadIdx.x & 31;
    const int t = blockIdx.x * 8 + warp;
    if (t >= N_) return;
    float probs[E_]; int i1, i2;
    router_core(g_x2 + (long)t * D_, rw, rb, lane, probs, &i1, &i2);
    if (lane == 0) {
        float gs = probs[i1] + probs[i2];
        g_topi[t * 2] = i1; g_topi[t * 2 + 1] = i2;
        g_gate[t * 2] = probs[i1] / gs; g_gate[t * 2 + 1] = probs[i2] / gs;
        atomicAdd(&g_cnt[i1], 1); atomicAdd(&g_cnt[i2], 1);
    }
}

__global__ void k_scan()
{
    if (threadIdx.x == 0) {
        int s = 0;
        for (int e = 0; e < E_; e++) { g_off[e] = s; s += g_cnt[e]; }
    }
}

__global__ void k_fill()
{
    int t = blockIdx.x * 256 + threadIdx.x;
    if (t >= N_) return;
#pragma unroll
    for (int k = 0; k < K_; k++) {
        int e = g_topi[t * K_ + k];
        int p = atomicAdd(&g_cur[e], 1);
        int d = g_off[e] + p;
        g_dtok[d] = t;
        g_dgate[d] = g_gate[t * K_ + k];
    }
}

__global__ void k_aux_router(const float* __restrict__ X,
                             const float* __restrict__ rw, const float* __restrict__ rb)
{
    const int warp = threadIdx.x >> 5, lane = threadIdx.x & 31;
    const int t = blockIdx.x * 8 + warp;
    if (t >= N_) return;
    float probs[E_]; int i1, i2;
    router_core(X + (long)t * D_, rw, rb, lane, probs, &i1, &i2);
    if (lane == 0) {
#pragma unroll
        for (int e = 0; e < E_; e++) g_probs[t * E_ + e] = probs[e];
        atomicAdd(&g_loadcnt[i1], 1); atomicAdd(&g_loadcnt[i2], 1);
    }
}

__global__ void k_aux_reduce(float* __restrict__ out, int write)
{
    __shared__ float red[256];
    const int tid = threadIdx.x;
    float imp[E_];
#pragma unroll
    for (int e = 0; e < E_; e++) imp[e] = 0.f;
    for (int t = tid; t < N_; t += 256)
#pragma unroll
        for (int e = 0; e < E_; e++) imp[e] += g_probs[t * E_ + e];
    float aux = 0.f;
    for (int e = 0; e < E_; e++) {
        red[tid] = imp[e]; __syncthreads();
        for (int o = 128; o > 0; o >>= 1) { if (tid < o) red[tid] += red[tid + o]; __syncthreads(); }
        if (tid == 0)
            aux += (red[0] / (float)N_) * ((float)g_loadcnt[e] / (float)(N_ * K_));
        __syncthreads();
    }
    if (tid == 0 && write) out[ND_] = aux * (float)E_;
}

// ---------------- launch ------------------------------------------------------
extern "C" void kernel_launch(void* const* d_in, const int* in_sizes, int n_in,
                              void* d_out, int out_size)
{
    (void)in_sizes; (void)n_in;
    const float* x     = (const float*)d_in[0];
    const float* enc   = (const float*)d_in[1];
    const float* sa_wq = (const float*)d_in[2];
    const float* sa_bq = (const float*)d_in[3];
    const float* sa_wk = (const float*)d_in[4];
    const float* sa_bk = (const float*)d_in[5];
    const float* sa_wv = (const float*)d_in[6];
    const float* sa_bv = (const float*)d_in[7];
    const float* sa_wo = (const float*)d_in[8];
    const float* sa_bo = (const float*)d_in[9];
    const float* ca_wq = (const float*)d_in[10];
    const float* ca_bq = (const float*)d_in[11];
    const float* ca_wk = (const float*)d_in[12];
    const float* ca_bk = (const float*)d_in[13];
    const float* ca_wv = (const float*)d_in[14];
    const float* ca_bv = (const float*)d_in[15];
    const float* ca_wo = (const float*)d_in[16];
    const float* ca_bo = (const float*)d_in[17];
    const float* n1_g  = (const float*)d_in[18];
    const float* n1_b  = (const float*)d_in[19];
    const float* n2_g  = (const float*)d_in[20];
    const float* n2_b  = (const float*)d_in[21];
    const float* n3_g  = (const float*)d_in[22];
    const float* n3_b  = (const float*)d_in[23];
    const float* r_w   = (const float*)d_in[24];
    const float* r_b   = (const float*)d_in[25];
    const float* e_w1  = (const float*)d_in[26];
    const float* e_b1  = (const float*)d_in[27];
    const float* e_w2  = (const float*)d_in[28];
    const float* e_b2  = (const float*)d_in[29];
    float* out = (float*)d_out;

    float *pq, *pk, *pv, *pattn, *pt, *px1, *px2, *pmoe;
    cudaGetSymbolAddress((void**)&pq, g_q);
    cudaGetSymbolAddress((void**)&pk, g_k);
    cudaGetSymbolAddress((void**)&pv, g_v);
    cudaGetSymbolAddress((void**)&pattn, g_attn);
    cudaGetSymbolAddress((void**)&pt, g_t);
    cudaGetSymbolAddress((void**)&px1, g_x1);
    cudaGetSymbolAddress((void**)&px2, g_x2);
    cudaGetSymbolAddress((void**)&pmoe, g_moe);

    static int s_attr_done = 0;
    if (!s_attr_done) {
        cudaFuncSetAttribute(k_flash, cudaFuncAttributeMaxDynamicSharedMemorySize,
                             FL_SMEM_WORDS * 4);
        s_attr_done = 1;
    }

    dim3 blk(256);
    dim3 gP3(D_ / 128, N_ / 128, 3);           // (8, 32, 3) = 768 blocks
    dim3 gP1(D_ / 128, N_ / 128);              // (8, 32)
    dim3 gFlash(S_ / 128, BH_);                // (16, 32)

    k_zero<<<(N_ * D_) / 256, blk>>>();

    // ---- self attention ----
    k_proj3<<<gP3, blk>>>(x, x, x, sa_wq, sa_wk, sa_wv, sa_bq, sa_bk, sa_bv,
                          pq, pk, pv);
    k_flash<<<gFlash, blk, FL_SMEM_WORDS * 4>>>();
    k_proj1<<<gP1, blk>>>(pattn, sa_wo, sa_bo, pt);
    k_addln<<<N_, blk>>>(x, pt, n1_g, n1_b, px1);

    // ---- cross attention ----
    k_proj3<<<gP3, blk>>>(px1, enc, enc, ca_wq, ca_wk, ca_wv, ca_bq, ca_bk, ca_bv,
                          pq, pk, pv);
    k_flash<<<gFlash, blk, FL_SMEM_WORDS * 4>>>();
    k_proj1<<<gP1, blk>>>(pattn, ca_wo, ca_bo, pt);
    k_addln<<<N_, blk>>>(px1, pt, n2_g, n2_b, px2);

    // ---- MoE (sparse top-2 dispatch) ----
    k_router<<<N_ / 8, blk>>>(r_w, r_b);
    k_scan<<<1, 32>>>();
    k_fill<<<N_ / 256, blk>>>();
    k_ff1<<<dim3(F_ / 128, 64, E_), blk>>>(e_w1, e_b1);
    k_ff2<<<dim3(D_ / 128, 64, E_), blk>>>(e_w2, e_b2);
    k_addln<<<N_, blk>>>(px2, pmoe, n3_g, n3_b, out);

    // ---- aux loss on final output ----
    k_aux_router<<<N_ / 8, blk>>>(out, r_w, r_b);
    k_aux_reduce<<<1, blk>>>(out, ((long)out_size > ND_) ? 1 : 0);
}